// round 13
// baseline (speedup 1.0000x reference)
#include <cuda_runtime.h>
#include <cuda_bf16.h>
#include <cstdint>

#define SSTEPS 16
#define NN 32768
#define EE 131072

// -------- persistent state (device globals; no allocation allowed) --------
__device__ float g_hs[(size_t)2 * EE * 64];    // ping-pong spatial h
__device__ float g_cs[(size_t)EE * 64];
__device__ float g_ht3[(size_t)3 * NN * 64];   // triple-buffered temporal h
__device__ float g_ct[(size_t)NN * 64];
__device__ float g_hn[(size_t)NN * 128];
__device__ float g_cn[(size_t)NN * 128];
__device__ float g_agg2[(size_t)2 * NN * 64];  // double-buffered agg

// pre-split, gate-interleaved, n-major weights (bf16, k' = [hi | lo])
__device__ __nv_bfloat16 g_w2t_s[256 * 256];
__device__ __nv_bfloat16 g_w2t_t[256 * 256];
__device__ __nv_bfloat16 g_w2t_n[512 * 512];

// node input planes: [enc(64) | emb(64) | hn_snapshot(128)] pre-split bf16
__device__ __nv_bfloat16 g_xeh[(size_t)NN * 256];
__device__ __nv_bfloat16 g_xel[(size_t)NN * 256];

__device__ __forceinline__ float sigf(float x)   { return 1.f / (1.f + __expf(-x)); }
__device__ __forceinline__ float tanh_f(float x) { return 2.f / (1.f + __expf(-2.f * x)) - 1.f; }

__device__ __forceinline__ void split_bf16(float v, __nv_bfloat16& hi, __nv_bfloat16& lo) {
    hi = __float2bfloat16(v);
    lo = __float2bfloat16(v - __bfloat162float(hi));
}

__device__ __forceinline__ void split2_store(char* baseHi, char* baseLo, uint32_t off,
                                             float v0, float v1) {
    __nv_bfloat16 h0, l0, h1, l1;
    split_bf16(v0, h0, l0);
    split_bf16(v1, h1, l1);
    *(__nv_bfloat162*)(baseHi + off) = __halves2bfloat162(h0, h1);
    *(__nv_bfloat162*)(baseLo + off) = __halves2bfloat162(l0, l1);
}

__device__ __forceinline__ uint32_t smem_u32(const void* p) {
    return (uint32_t)__cvta_generic_to_shared(p);
}

#define LDSM4(r0, r1, r2, r3, addr) \
    asm volatile("ldmatrix.sync.aligned.m8n8.x4.shared.b16 {%0,%1,%2,%3},[%4];" \
                 : "=r"(r0), "=r"(r1), "=r"(r2), "=r"(r3) : "r"(addr))

#define MMA_BF16(D, a0, a1, a2, a3, b0, b1) \
    asm volatile("mma.sync.aligned.m16n8k16.row.col.f32.bf16.bf16.f32 " \
                 "{%0,%1,%2,%3},{%4,%5,%6,%7},{%8,%9},{%0,%1,%2,%3};" \
                 : "+f"(D[0]), "+f"(D[1]), "+f"(D[2]), "+f"(D[3]) \
                 : "r"(a0), "r"(a1), "r"(a2), "r"(a3), "r"(b0), "r"(b1))

#define CP16(saddr, gptr) \
    asm volatile("cp.async.cg.shared.global [%0],[%1],16;" :: "r"(saddr), "l"(gptr))
#define CP_COMMIT() asm volatile("cp.async.commit_group;")
#define CP_WAIT0()  asm volatile("cp.async.wait_group 0;")
#define CP_WAIT1()  asm volatile("cp.async.wait_group 1;")

#define RED4(ptr, v) \
    asm volatile("red.global.add.v4.f32 [%0], {%1,%2,%3,%4};" \
                 :: "l"(ptr), "f"((v).x), "f"((v).y), "f"((v).z), "f"((v).w) : "memory")

// ============================================================================
// weight prep
// edge (N-split layout): rb = nh*128 + nwl*32 + g*8 + jj
//   -> orig_n = g*64 + nh*32 + nwl*8 + jj
// ============================================================================
__global__ void prep_edge_w(const float* __restrict__ Wih, const float* __restrict__ Whh,
                            __nv_bfloat16* __restrict__ W2t) {
    int idx = blockIdx.x * 256 + threadIdx.x;
    int rb = idx >> 7, k = idx & 127;
    int nh = rb >> 7, nwl = (rb >> 5) & 3, g = (rb >> 3) & 3, jj = rb & 7;
    int orig_n = g * 64 + nh * 32 + nwl * 8 + jj;
    float v = (k < 64) ? Wih[k * 256 + orig_n] : Whh[(k - 64) * 256 + orig_n];
    __nv_bfloat16 hi, lo; split_bf16(v, hi, lo);
    W2t[rb * 256 + k] = hi;
    W2t[rb * 256 + 128 + k] = lo;
}

// node rb = nh*256 + nw*64 + g*16 + jj -> orig_n = g*128 + nh*64 + nw*16 + jj
__global__ void prep_node_w(const float* __restrict__ Wih, const float* __restrict__ Whh,
                            __nv_bfloat16* __restrict__ W2t) {
    int idx = blockIdx.x * 256 + threadIdx.x;
    int rb = idx >> 8, k = idx & 255;
    int nh = rb >> 8, nw = (rb >> 6) & 3, g = (rb >> 4) & 3, jj = rb & 15;
    int orig_n = g * 128 + nh * 64 + nw * 16 + jj;
    float v = (k < 128) ? Wih[k * 512 + orig_n] : Whh[(k - 128) * 512 + orig_n];
    __nv_bfloat16 hi, lo; split_bf16(v, hi, lo);
    W2t[rb * 512 + k] = hi;
    W2t[rb * 512 + 256 + k] = lo;
}

// ============================================================================
// Edge LSTM (hidden 64, K=128), merged spatial+temporal, N-SPLIT grid.y=2.
// Block = 64 rows x N-half (128 gate-rows = 32 hidden cells, all gates).
// 8 warps (2M x 4N), warp tile m32 x n32 (4 gates x 8 cells). 3 blocks/SM.
// ALL h states read from *_in and written to *_out (ping-pong) — the
// N-split halves read full h rows but write disjoint 32-col slices.
// SMEM: Ahi [64][136]bf16 17408 | Alo 17408 | Cs_in [64 x 144B] 9216 |
//       inc 512 | 3x Bbuf [128 x 80B] 10240
// ============================================================================
#define E_AHI 0
#define E_ALO 17408
#define E_CS  34816
#define E_INC 44032
#define E_BUF 44544
#define E_BUFSZ 10240
#define EDGE_SMEM (44544 + 3 * 10240)
#define SE_BLOCKS (EE / 64)

__global__ __launch_bounds__(256, 3) void edge_mma5_kernel(
    const float* __restrict__ x_s, const float* __restrict__ x_t,
    const float* __restrict__ encw_s, const float* __restrict__ encb_s,
    const float* __restrict__ encw_t, const float* __restrict__ encb_t,
    const __nv_bfloat16* __restrict__ W2t_s, const __nv_bfloat16* __restrict__ W2t_t,
    const float* __restrict__ bias_s, const float* __restrict__ bias_t,
    const float* __restrict__ h_s_in, float* __restrict__ h_s_out,
    float* __restrict__ c_s,
    const float* __restrict__ h_t_in, float* __restrict__ h_t_out,
    float* __restrict__ c_t,
    float* __restrict__ agg, const int* __restrict__ inc)
{
    extern __shared__ char sm[];
    const uint32_t sb = smem_u32(sm);
    const int tid = threadIdx.x;
    const int wid = tid >> 5, l = tid & 31;
    const int mw = wid & 1, nwl = wid >> 1;
    const int m0 = mw * 32;
    const int nh = blockIdx.y;

    const bool is_se = (blockIdx.x < SE_BLOCKS);
    const int row0 = (is_se ? blockIdx.x : (blockIdx.x - SE_BLOCKS)) * 64;
    const float* x    = is_se ? x_s : x_t;
    const float* encw = is_se ? encw_s : encw_t;
    const float* encb = is_se ? encb_s : encb_t;
    const __nv_bfloat16* W2t = is_se ? W2t_s : W2t_t;
    const float* bias = is_se ? bias_s : bias_t;
    const float* hIn = is_se ? h_s_in : h_t_in;
    float* hOut = is_se ? h_s_out : h_t_out;
    float* c = is_se ? c_s : c_t;
    float* aggp = is_se ? agg : nullptr;

    const __nv_bfloat16* Wb = W2t + (size_t)(nh * 128) * 256;   // this half's rows

    // ---- group 0: B chunk0 + Cs_in slice + inc ----
    #pragma unroll
    for (int it = 0; it < 2; ++it) {
        int idx = tid + it * 256;
        int r = idx >> 2, k8 = idx & 3;
        CP16(sb + E_BUF + r * 80 + k8 * 16, Wb + (size_t)r * 256 + 0 * 32 + k8 * 8);
    }
    #pragma unroll
    for (int it = 0; it < 2; ++it) {
        int idx = tid + it * 256;                 // 512 = 64r x 8 seg
        int r = idx >> 3, seg = idx & 7;
        CP16(sb + E_CS + r * 144 + seg * 16,
             c + (size_t)(row0 + r) * 64 + nh * 32 + seg * 4);
    }
    if (is_se && tid < 32)
        CP16(sb + E_INC + tid * 16, inc + 2 * row0 + tid * 4);
    CP_COMMIT();
    // ---- group 1: B chunk1 ----
    #pragma unroll
    for (int it = 0; it < 2; ++it) {
        int idx = tid + it * 256;
        int r = idx >> 2, k8 = idx & 3;
        CP16(sb + E_BUF + E_BUFSZ + r * 80 + k8 * 16, Wb + (size_t)r * 256 + 1 * 32 + k8 * 8);
    }
    CP_COMMIT();

    // ---- stage A (enc cols 0..63, h cols 64..127), split planes ----
    #pragma unroll
    for (int it = 0; it < 8; ++it) {
        int idx = tid + it * 256;
        int r = idx >> 5, j4 = idx & 31;
        int R = row0 + r;
        if (j4 < 16) {
            float x0 = x[R * 2 + 0], x1 = x[R * 2 + 1];
            int j = j4 * 4;
            #pragma unroll
            for (int e = 0; e < 2; ++e) {
                int cc = j + e * 2;
                float v0 = fmaxf(fmaf(x0, __ldg(&encw[cc]),     fmaf(x1, __ldg(&encw[64 + cc]),     __ldg(&encb[cc]))), 0.f);
                float v1 = fmaxf(fmaf(x0, __ldg(&encw[cc + 1]), fmaf(x1, __ldg(&encw[64 + cc + 1]), __ldg(&encb[cc + 1]))), 0.f);
                split2_store(sm + E_AHI, sm + E_ALO, r * 272 + cc * 2, v0, v1);
            }
        } else {
            int j = (j4 - 16) * 4;
            float4 hv = *(const float4*)&hIn[(size_t)R * 64 + j];
            split2_store(sm + E_AHI, sm + E_ALO, r * 272 + (64 + j) * 2, hv.x, hv.y);
            split2_store(sm + E_AHI, sm + E_ALO, r * 272 + (64 + j + 2) * 2, hv.z, hv.w);
        }
    }

    // ---- lane-constant offsets ----
    const int qi = l >> 3, ii = l & 7;
    const uint32_t b_lane = ((qi >= 2 ? 8u : 0u) + (uint32_t)ii) * 80u + (qi & 1) * 16u;
    const uint32_t a_lane = (uint32_t)(l & 15) * 272u + (uint32_t)(l >> 4) * 16u;
    const uint32_t aHiB = sb + E_AHI + m0 * 272 + a_lane;
    const uint32_t aLoB = sb + E_ALO + m0 * 272 + a_lane;
    const uint32_t bWarp = nwl * 2560 + b_lane;     // nwl*32 rows * 80B

    float acc[2][4][4];
    #pragma unroll
    for (int mt = 0; mt < 2; ++mt)
        #pragma unroll
        for (int g = 0; g < 4; ++g)
            #pragma unroll
            for (int e = 0; e < 4; ++e) acc[mt][g][e] = 0.f;

    // ---- mainloop: 8 k32 chunks (hi 0..3, lo 4..7) ----
    for (int cc = 0; cc < 8; ++cc) {
        if (cc < 7) { CP_WAIT1(); } else { CP_WAIT0(); }
        __syncthreads();

        if (cc + 2 < 8) {
            const int cn2 = cc + 2;
            const uint32_t dstb = sb + E_BUF + (cn2 % 3) * E_BUFSZ;
            #pragma unroll
            for (int it = 0; it < 2; ++it) {
                int idx = tid + it * 256;
                int r = idx >> 2, k8 = idx & 3;
                CP16(dstb + r * 80 + k8 * 16, Wb + (size_t)r * 256 + cn2 * 32 + k8 * 8);
            }
            CP_COMMIT();
        }

        const uint32_t bufB = sb + E_BUF + (cc % 3) * E_BUFSZ + bWarp;
        const bool hiChunk = (cc < 4);
        const uint32_t acol = (uint32_t)(cc & 3) * 64;

        #pragma unroll
        for (int ks2 = 0; ks2 < 2; ++ks2) {
            uint32_t bb[4][2];
            #pragma unroll
            for (int fg = 0; fg < 2; ++fg) {
                uint32_t r0, r1, r2, r3;
                LDSM4(r0, r1, r2, r3, bufB + fg * 1280 + ks2 * 32);
                bb[fg * 2][0] = r0;     bb[fg * 2][1] = r1;
                bb[fg * 2 + 1][0] = r2; bb[fg * 2 + 1][1] = r3;
            }
            #pragma unroll
            for (int ap = 0; ap < 2; ++ap) {
                if (!hiChunk && ap == 1) continue;
                #pragma unroll
                for (int mt = 0; mt < 2; ++mt) {
                    uint32_t a0, a1, a2, a3;
                    LDSM4(a0, a1, a2, a3, (ap ? aLoB : aHiB) + mt * 4352 + acol + ks2 * 32);
                    #pragma unroll
                    for (int g = 0; g < 4; ++g)
                        MMA_BF16(acc[mt][g], a0, a1, a2, a3, bb[g][0], bb[g][1]);
                }
            }
        }
    }

    // ---- epilogue: gates -> staged h/c (stride 144B) in dead A region ----
    __syncthreads();

    const int jl = nwl * 8 + 2 * (l & 3);          // local col in [0,32)
    const int j0 = nh * 32 + jl;                   // global hidden col
    const int rl_base = m0 + (l >> 2);
    #pragma unroll
    for (int mt = 0; mt < 2; ++mt) {
        #pragma unroll
        for (int rh = 0; rh < 2; ++rh) {
            int rl = rl_base + mt * 16 + rh * 8;
            float i0 = acc[mt][0][rh * 2]     + __ldg(&bias[j0]);
            float i1 = acc[mt][0][rh * 2 + 1] + __ldg(&bias[j0 + 1]);
            float f0 = acc[mt][1][rh * 2]     + __ldg(&bias[64 + j0]);
            float f1 = acc[mt][1][rh * 2 + 1] + __ldg(&bias[64 + j0 + 1]);
            float g0 = acc[mt][2][rh * 2]     + __ldg(&bias[128 + j0]);
            float g1 = acc[mt][2][rh * 2 + 1] + __ldg(&bias[128 + j0 + 1]);
            float o0 = acc[mt][3][rh * 2]     + __ldg(&bias[192 + j0]);
            float o1 = acc[mt][3][rh * 2 + 1] + __ldg(&bias[192 + j0 + 1]);
            float2 cold = *(const float2*)(sm + E_CS + rl * 144 + jl * 4);
            float c0 = sigf(f0) * cold.x + sigf(i0) * tanh_f(g0);
            float c1 = sigf(f1) * cold.y + sigf(i1) * tanh_f(g1);
            float h0 = sigf(o0) * tanh_f(c0);
            float h1 = sigf(o1) * tanh_f(c1);
            *(float2*)(sm + rl * 144 + jl * 4)        = make_float2(h0, h1);
            *(float2*)(sm + 9216 + rl * 144 + jl * 4) = make_float2(c0, c1);
        }
    }
    __syncthreads();

    // ---- cooperative coalesced writeback + vector red scatter (32-col slice) ----
    const int* incs = (const int*)(sm + E_INC);
    #pragma unroll
    for (int p = 0; p < 2; ++p) {
        int r = p * 32 + (tid >> 3);
        int j4 = tid & 7;
        int R = row0 + r;
        float4 hv = *(const float4*)(sm + r * 144 + j4 * 16);
        float4 cv = *(const float4*)(sm + 9216 + r * 144 + j4 * 16);
        *(float4*)&hOut[(size_t)R * 64 + nh * 32 + j4 * 4] = hv;
        *(float4*)&c[(size_t)R * 64 + nh * 32 + j4 * 4] = cv;
        if (aggp) {
            int n0 = incs[2 * r], n1 = incs[2 * r + 1];
            RED4(&aggp[(size_t)n0 * 64 + nh * 32 + j4 * 4], hv);
            RED4(&aggp[(size_t)n1 * 64 + nh * 32 + j4 * 4], hv);
        }
    }
}

// ============================================================================
// emb kernel: enc/emb + hn snapshot into planes (unchanged).
// ============================================================================
#define EMB_SMEM (64 * 132 * 4 + 128 * 64 * 4)

__global__ __launch_bounds__(256) void emb_kernel(
    const float* __restrict__ xn,
    const float* __restrict__ nencw, const float* __restrict__ nencb,
    const float* __restrict__ eew,   const float* __restrict__ eeb,
    const float* __restrict__ ht,    const float* __restrict__ agg,
    const float* __restrict__ hn,
    __nv_bfloat16* __restrict__ xeh, __nv_bfloat16* __restrict__ xel)
{
    extern __shared__ float smf[];
    float* Asf  = smf;
    float* eewS = smf + 64 * 132;

    const int tid = threadIdx.x;
    const int row0 = blockIdx.x * 64;

    #pragma unroll
    for (int it = 0; it < 16; ++it) {
        int idx = tid + it * 256;
        int r = idx >> 6, j = idx & 63;
        int R = row0 + r;
        Asf[r * 132 + j]      = ht[(size_t)R * 64 + j];
        Asf[r * 132 + 64 + j] = agg[(size_t)R * 64 + j];
    }
    #pragma unroll
    for (int it = 0; it < 8; ++it) {
        int f4 = tid + it * 256;
        *(float4*)&eewS[f4 * 4] = *(const float4*)&eew[f4 * 4];
    }

    #pragma unroll
    for (int it = 0; it < 16; ++it) {
        int idx = tid + it * 256;
        int r = idx >> 6, jp = idx & 63;
        int R = row0 + r;
        float2 hv = *(const float2*)&hn[(size_t)R * 128 + jp * 2];
        split2_store((char*)(xeh + (size_t)R * 256), (char*)(xel + (size_t)R * 256),
                     (128 + jp * 2) * 2, hv.x, hv.y);
    }
    __syncthreads();

    const int r = tid >> 2, jq = tid & 3;
    const int R = row0 + r;

    {
        float xv = xn[R];
        #pragma unroll
        for (int u = 0; u < 8; ++u) {
            int cc = jq * 16 + u * 2;
            float v0 = fmaxf(fmaf(xv, __ldg(&nencw[cc]),     __ldg(&nencb[cc])), 0.f);
            float v1 = fmaxf(fmaf(xv, __ldg(&nencw[cc + 1]), __ldg(&nencb[cc + 1])), 0.f);
            split2_store((char*)(xeh + (size_t)R * 256), (char*)(xel + (size_t)R * 256),
                         cc * 2, v0, v1);
        }
    }

    {
        float accv[16];
        #pragma unroll
        for (int u = 0; u < 16; ++u) accv[u] = __ldg(&eeb[jq * 16 + u]);
        #pragma unroll 4
        for (int k = 0; k < 128; ++k) {
            float a = Asf[r * 132 + k];
            #pragma unroll
            for (int g = 0; g < 4; ++g) {
                float4 w4 = *(const float4*)&eewS[k * 64 + jq * 16 + g * 4];
                accv[g*4+0] = fmaf(a, w4.x, accv[g*4+0]);
                accv[g*4+1] = fmaf(a, w4.y, accv[g*4+1]);
                accv[g*4+2] = fmaf(a, w4.z, accv[g*4+2]);
                accv[g*4+3] = fmaf(a, w4.w, accv[g*4+3]);
            }
        }
        #pragma unroll
        for (int u = 0; u < 8; ++u) {
            float v0 = fmaxf(accv[u * 2], 0.f);
            float v1 = fmaxf(accv[u * 2 + 1], 0.f);
            int cc = 64 + jq * 16 + u * 2;
            split2_store((char*)(xeh + (size_t)R * 256), (char*)(xel + (size_t)R * 256),
                         cc * 2, v0, v1);
        }
    }
}

// ============================================================================
// Node LSTM GEMM (hidden 128, K=256). Grid (NN/64, 2). Unchanged from R10.
// ============================================================================
#define N_AHI 0
#define N_ALO 33792
#define N_BUF 67584
#define N_BUFSZ 12288
#define NODE_SMEM (67584 + 3 * 12288)

__global__ __launch_bounds__(256, 2) void node_mma4_kernel(
    const __nv_bfloat16* __restrict__ xeh, const __nv_bfloat16* __restrict__ xel,
    const __nv_bfloat16* __restrict__ W2t,
    const float* __restrict__ bias,
    const float* __restrict__ outw,  const float* __restrict__ outb,
    float* __restrict__ hn, float* __restrict__ cn,
    float* __restrict__ out)
{
    extern __shared__ char sm[];
    const uint32_t sb = smem_u32(sm);
    const int tid = threadIdx.x;
    const int wid = tid >> 5, l = tid & 31;
    const int mw = wid & 1, nw = wid >> 1;
    const int m0 = mw * 32;
    const int row0 = blockIdx.x * 64;
    const int nh = blockIdx.y;
    const __nv_bfloat16* Wb = W2t + (size_t)(nh * 256) * 512;

    #pragma unroll
    for (int it = 0; it < 16; ++it) {
        int idx = tid + it * 256;
        int plane = idx >> 11;
        int i2 = idx & 2047;
        int r = i2 >> 5, k8 = i2 & 31;
        const __nv_bfloat16* src = (plane ? xel : xeh) + (size_t)(row0 + r) * 256 + k8 * 8;
        CP16(sb + (plane ? N_ALO : N_AHI) + r * 528 + k8 * 16, src);
    }
    CP_COMMIT();

    #pragma unroll
    for (int it = 0; it < 2; ++it) {
        int idx = tid + it * 256;
        int r = idx >> 1, k8 = idx & 1;
        CP16(sb + N_BUF + r * 48 + k8 * 16, Wb + (size_t)r * 512 + 0 * 16 + k8 * 8);
    }
    CP_COMMIT();
    #pragma unroll
    for (int it = 0; it < 2; ++it) {
        int idx = tid + it * 256;
        int r = idx >> 1, k8 = idx & 1;
        CP16(sb + N_BUF + N_BUFSZ + r * 48 + k8 * 16, Wb + (size_t)r * 512 + 1 * 16 + k8 * 8);
    }
    CP_COMMIT();

    float2 cold[2][2][2];
    #pragma unroll
    for (int mt = 0; mt < 2; ++mt)
        #pragma unroll
        for (int rh = 0; rh < 2; ++rh)
            #pragma unroll
            for (int u = 0; u < 2; ++u) {
                int R = row0 + m0 + (l >> 2) + mt * 16 + rh * 8;
                int j0 = nh * 64 + nw * 16 + u * 8 + 2 * (l & 3);
                cold[mt][rh][u] = __ldg((const float2*)&cn[(size_t)R * 128 + j0]);
            }

    const int qi = l >> 3, ii = l & 7;
    const uint32_t b_lane = ((qi >= 2 ? 8u : 0u) + (uint32_t)ii) * 48u + (qi & 1) * 16u;
    const uint32_t a_lane = (uint32_t)(l & 15) * 528u + (uint32_t)(l >> 4) * 16u;
    const uint32_t aHiB = sb + N_AHI + m0 * 528 + a_lane;
    const uint32_t aLoB = sb + N_ALO + m0 * 528 + a_lane;
    const uint32_t bWarp = nw * 3072 + b_lane;

    float acc[2][8][4];
    #pragma unroll
    for (int mt = 0; mt < 2; ++mt)
        #pragma unroll
        for (int nt = 0; nt < 8; ++nt)
            #pragma unroll
            for (int e = 0; e < 4; ++e) acc[mt][nt][e] = 0.f;

    for (int cc = 0; cc < 32; ++cc) {
        if (cc < 31) { CP_WAIT1(); } else { CP_WAIT0(); }
        __syncthreads();

        if (cc + 2 < 32) {
            const int cn2 = cc + 2;
            const uint32_t dstb = sb + N_BUF + (cn2 % 3) * N_BUFSZ;
            #pragma unroll
            for (int it = 0; it < 2; ++it) {
                int idx = tid + it * 256;
                int r = idx >> 1, k8 = idx & 1;
                CP16(dstb + r * 48 + k8 * 16, Wb + (size_t)r * 512 + cn2 * 16 + k8 * 8);
            }
            CP_COMMIT();
        }

        const uint32_t bufB = sb + N_BUF + (cc % 3) * N_BUFSZ + bWarp;
        const bool hiChunk = (cc < 16);
        const uint32_t acol = (uint32_t)(cc & 15) * 32;

        uint32_t bb[8][2];
        #pragma unroll
        for (int fg = 0; fg < 4; ++fg) {
            uint32_t r0, r1, r2, r3;
            LDSM4(r0, r1, r2, r3, bufB + fg * 768);
            bb[fg * 2][0] = r0;     bb[fg * 2][1] = r1;
            bb[fg * 2 + 1][0] = r2; bb[fg * 2 + 1][1] = r3;
        }
        #pragma unroll
        for (int ap = 0; ap < 2; ++ap) {
            if (!hiChunk && ap == 1) continue;
            #pragma unroll
            for (int mt = 0; mt < 2; ++mt) {
                uint32_t a0, a1, a2, a3;
                LDSM4(a0, a1, a2, a3, (ap ? aLoB : aHiB) + mt * 8448 + acol);
                #pragma unroll
                for (int nt = 0; nt < 8; ++nt)
                    MMA_BF16(acc[mt][nt], a0, a1, a2, a3, bb[nt][0], bb[nt][1]);
            }
        }
    }

    __syncthreads();

    const float ob = (nh == 0 && nw == 0) ? __ldg(outb) : 0.f;
    const int rl_base = m0 + (l >> 2);
    #pragma unroll
    for (int mt = 0; mt < 2; ++mt) {
        #pragma unroll
        for (int rh = 0; rh < 2; ++rh) {
            int rl = rl_base + mt * 16 + rh * 8;
            int R = row0 + rl;
            float po = 0.f;
            #pragma unroll
            for (int u = 0; u < 2; ++u) {
                int j0 = nh * 64 + nw * 16 + u * 8 + 2 * (l & 3);
                int jl = j0 - nh * 64;
                float i0 = acc[mt][u][rh * 2]          + __ldg(&bias[j0]);
                float i1 = acc[mt][u][rh * 2 + 1]      + __ldg(&bias[j0 + 1]);
                float f0 = acc[mt][2 + u][rh * 2]      + __ldg(&bias[128 + j0]);
                float f1 = acc[mt][2 + u][rh * 2 + 1]  + __ldg(&bias[128 + j0 + 1]);
                float g0 = acc[mt][4 + u][rh * 2]      + __ldg(&bias[256 + j0]);
                float g1 = acc[mt][4 + u][rh * 2 + 1]  + __ldg(&bias[256 + j0 + 1]);
                float o0 = acc[mt][6 + u][rh * 2]      + __ldg(&bias[384 + j0]);
                float o1 = acc[mt][6 + u][rh * 2 + 1]  + __ldg(&bias[384 + j0 + 1]);
                float2 cv = cold[mt][rh][u];
                float c0 = sigf(f0) * cv.x + sigf(i0) * tanh_f(g0);
                float c1 = sigf(f1) * cv.y + sigf(i1) * tanh_f(g1);
                float h0 = sigf(o0) * tanh_f(c0);
                float h1 = sigf(o1) * tanh_f(c1);
                *(float2*)(sm + rl * 272 + jl * 4)         = make_float2(h0, h1);
                *(float2*)(sm + 17408 + rl * 272 + jl * 4) = make_float2(c0, c1);
                po = fmaf(h0, __ldg(&outw[j0]), po);
                po = fmaf(h1, __ldg(&outw[j0 + 1]), po);
            }
            po += __shfl_xor_sync(0xffffffffu, po, 1);
            po += __shfl_xor_sync(0xffffffffu, po, 2);
            if ((l & 3) == 0) atomicAdd(&out[R], po + ob);
        }
    }
    __syncthreads();

    #pragma unroll
    for (int p = 0; p < 4; ++p) {
        int r = p * 16 + (tid >> 4);
        int j4 = tid & 15;
        int R = row0 + r;
        float4 hv = *(const float4*)(sm + r * 272 + j4 * 16);
        float4 cv = *(const float4*)(sm + 17408 + r * 272 + j4 * 16);
        *(float4*)&hn[(size_t)R * 128 + nh * 64 + j4 * 4] = hv;
        *(float4*)&cn[(size_t)R * 128 + nh * 64 + j4 * 4] = cv;
    }
}

// ============================================================================
extern "C" void kernel_launch(void* const* d_in, const int* in_sizes, int n_in,
                              void* d_out, int out_size) {
    const float* data_nodes = (const float*)d_in[0];
    const float* data_te    = (const float*)d_in[1];
    const float* data_se    = (const float*)d_in[2];
    const float* h_n0 = (const float*)d_in[3];
    const float* c_n0 = (const float*)d_in[4];
    const float* h_t0 = (const float*)d_in[5];
    const float* c_t0 = (const float*)d_in[6];
    const float* h_s0 = (const float*)d_in[7];
    const float* c_s0 = (const float*)d_in[8];
    const int*   inc  = (const int*)d_in[9];
    const float* t_enc_w = (const float*)d_in[10];
    const float* t_enc_b = (const float*)d_in[11];
    const float* t_Wih   = (const float*)d_in[12];
    const float* t_Whh   = (const float*)d_in[13];
    const float* t_b     = (const float*)d_in[14];
    const float* s_enc_w = (const float*)d_in[15];
    const float* s_enc_b = (const float*)d_in[16];
    const float* s_Wih   = (const float*)d_in[17];
    const float* s_Whh   = (const float*)d_in[18];
    const float* s_b     = (const float*)d_in[19];
    const float* n_enc_w = (const float*)d_in[20];
    const float* n_enc_b = (const float*)d_in[21];
    const float* ee_w    = (const float*)d_in[22];
    const float* ee_b    = (const float*)d_in[23];
    const float* n_Wih   = (const float*)d_in[24];
    const float* n_Whh   = (const float*)d_in[25];
    const float* n_b     = (const float*)d_in[26];
    const float* out_w   = (const float*)d_in[27];
    const float* out_b   = (const float*)d_in[28];
    float* out = (float*)d_out;

    float *hs, *cs, *ht3, *ct, *hn, *cn, *agg2;
    __nv_bfloat16 *w2t_s, *w2t_t, *w2t_n, *xeh, *xel;
    cudaGetSymbolAddress((void**)&hs,  g_hs);
    cudaGetSymbolAddress((void**)&cs,  g_cs);
    cudaGetSymbolAddress((void**)&ht3, g_ht3);
    cudaGetSymbolAddress((void**)&ct,  g_ct);
    cudaGetSymbolAddress((void**)&hn,  g_hn);
    cudaGetSymbolAddress((void**)&cn,  g_cn);
    cudaGetSymbolAddress((void**)&agg2, g_agg2);
    cudaGetSymbolAddress((void**)&w2t_s, g_w2t_s);
    cudaGetSymbolAddress((void**)&w2t_t, g_w2t_t);
    cudaGetSymbolAddress((void**)&w2t_n, g_w2t_n);
    cudaGetSymbolAddress((void**)&xeh, g_xeh);
    cudaGetSymbolAddress((void**)&xel, g_xel);

    static bool s_init = false;
    static cudaStream_t s1, s2;
    static cudaEvent_t evRoot, evJ1, evJ2;
    static cudaEvent_t evEdge[SSTEPS], evEmb[SSTEPS];
    if (!s_init) {
        s_init = true;
        cudaStreamCreateWithFlags(&s1, cudaStreamNonBlocking);
        cudaStreamCreateWithFlags(&s2, cudaStreamNonBlocking);
        cudaEventCreateWithFlags(&evRoot, cudaEventDisableTiming);
        cudaEventCreateWithFlags(&evJ1, cudaEventDisableTiming);
        cudaEventCreateWithFlags(&evJ2, cudaEventDisableTiming);
        for (int t = 0; t < SSTEPS; ++t) {
            cudaEventCreateWithFlags(&evEdge[t], cudaEventDisableTiming);
            cudaEventCreateWithFlags(&evEmb[t], cudaEventDisableTiming);
        }
        cudaFuncSetAttribute(edge_mma5_kernel, cudaFuncAttributeMaxDynamicSharedMemorySize, EDGE_SMEM);
        cudaFuncSetAttribute(node_mma4_kernel, cudaFuncAttributeMaxDynamicSharedMemorySize, NODE_SMEM);
        cudaFuncSetAttribute(emb_kernel,       cudaFuncAttributeMaxDynamicSharedMemorySize, EMB_SMEM);
    }

    // ---- prologue on the capture (default) stream ----
    cudaMemcpyAsync(hs, h_s0, (size_t)EE * 64  * 4, cudaMemcpyDeviceToDevice);  // buffer 0
    cudaMemcpyAsync(cs, c_s0, (size_t)EE * 64  * 4, cudaMemcpyDeviceToDevice);
    cudaMemcpyAsync(ht3, h_t0, (size_t)NN * 64 * 4, cudaMemcpyDeviceToDevice);
    cudaMemcpyAsync(ct, c_t0, (size_t)NN * 64  * 4, cudaMemcpyDeviceToDevice);
    cudaMemcpyAsync(hn, h_n0, (size_t)NN * 128 * 4, cudaMemcpyDeviceToDevice);
    cudaMemcpyAsync(cn, c_n0, (size_t)NN * 128 * 4, cudaMemcpyDeviceToDevice);
    cudaMemsetAsync(out, 0, (size_t)SSTEPS * NN * 4);

    prep_edge_w<<<128, 256>>>(s_Wih, s_Whh, w2t_s);
    prep_edge_w<<<128, 256>>>(t_Wih, t_Whh, w2t_t);
    prep_node_w<<<512, 256>>>(n_Wih, n_Whh, w2t_n);

    // ---- fork ----
    cudaEventRecord(evRoot, 0);
    cudaStreamWaitEvent(s1, evRoot, 0);
    cudaStreamWaitEvent(s2, evRoot, 0);

    const int edge_grid_x = SE_BLOCKS + NN / 64;   // 2048 + 512
    const size_t HTB = (size_t)NN * 64;
    const size_t HSB = (size_t)EE * 64;

    for (int t = 0; t < SSTEPS; ++t) {
        float* aggT  = agg2 + (size_t)(t & 1) * HTB;
        float* htIn  = ht3 + (size_t)(t % 3) * HTB;
        float* htOut = ht3 + (size_t)((t + 1) % 3) * HTB;
        float* hsIn  = hs + (size_t)(t & 1) * HSB;
        float* hsOut = hs + (size_t)((t + 1) & 1) * HSB;

        if (t >= 2) cudaStreamWaitEvent(s1, evEmb[t - 2], 0);
        cudaMemsetAsync(aggT, 0, HTB * 4, s1);
        edge_mma5_kernel<<<dim3(edge_grid_x, 2), 256, EDGE_SMEM, s1>>>(
            data_se + (size_t)t * EE * 2, data_te + (size_t)t * NN * 2,
            s_enc_w, s_enc_b, t_enc_w, t_enc_b,
            w2t_s, w2t_t, s_b, t_b,
            hsIn, hsOut, cs, htIn, htOut, ct, aggT, inc);
        cudaEventRecord(evEdge[t], s1);

        cudaStreamWaitEvent(s2, evEdge[t], 0);
        emb_kernel<<<NN / 64, 256, EMB_SMEM, s2>>>(
            data_nodes + (size_t)t * NN,
            n_enc_w, n_enc_b, ee_w, ee_b,
            htOut, aggT, hn, xeh, xel);
        cudaEventRecord(evEmb[t], s2);
        node_mma4_kernel<<<dim3(NN / 64, 2), 256, NODE_SMEM, s2>>>(
            xeh, xel, w2t_n, n_b, out_w, out_b,
            hn, cn, out + (size_t)t * NN);
    }

    // ---- join back to the capture stream ----
    cudaEventRecord(evJ1, s1);
    cudaEventRecord(evJ2, s2);
    cudaStreamWaitEvent(0, evJ1, 0);
    cudaStreamWaitEvent(0, evJ2, 0);
}

// round 14
// speedup vs baseline: 1.4417x; 1.4417x over previous
#include <cuda_runtime.h>
#include <cuda_fp16.h>
#include <cstdint>

#define SSTEPS 16
#define NN 32768
#define EE 131072

// -------- persistent state (device globals; no allocation allowed) --------
__device__ __half g_hsp[(size_t)2 * EE * 64];   // ping-pong spatial h (fp16 plane)
__device__ float  g_cs[(size_t)EE * 64];
__device__ __half g_htp[(size_t)3 * NN * 64];   // triple-buffered temporal h (fp16)
__device__ float  g_ct[(size_t)NN * 64];
__device__ float  g_hn[(size_t)NN * 128];
__device__ float  g_cn[(size_t)NN * 128];
__device__ float  g_agg2[(size_t)2 * NN * 64];  // double-buffered agg

// pre-split (hi|lo along k'), gate-interleaved, n-major weights (fp16)
__device__ __half g_w2t_s[256 * 256];
__device__ __half g_w2t_t[256 * 256];
__device__ __half g_w2t_n[512 * 512];

// node input plane: [enc(64) | emb(64) | hn_snapshot(128)] fp16
__device__ __half g_xe[(size_t)NN * 256];

__device__ __forceinline__ float sigf(float x)   { return 1.f / (1.f + __expf(-x)); }
__device__ __forceinline__ float tanh_f(float x) { return 2.f / (1.f + __expf(-2.f * x)) - 1.f; }

__device__ __forceinline__ void split_f16(float v, __half& hi, __half& lo) {
    hi = __float2half(v);
    lo = __float2half(v - __half2float(hi));
}

__device__ __forceinline__ uint32_t smem_u32(const void* p) {
    return (uint32_t)__cvta_generic_to_shared(p);
}

#define LDSM4(r0, r1, r2, r3, addr) \
    asm volatile("ldmatrix.sync.aligned.m8n8.x4.shared.b16 {%0,%1,%2,%3},[%4];" \
                 : "=r"(r0), "=r"(r1), "=r"(r2), "=r"(r3) : "r"(addr))

#define MMA_F16(D, a0, a1, a2, a3, b0, b1) \
    asm volatile("mma.sync.aligned.m16n8k16.row.col.f32.f16.f16.f32 " \
                 "{%0,%1,%2,%3},{%4,%5,%6,%7},{%8,%9},{%0,%1,%2,%3};" \
                 : "+f"(D[0]), "+f"(D[1]), "+f"(D[2]), "+f"(D[3]) \
                 : "r"(a0), "r"(a1), "r"(a2), "r"(a3), "r"(b0), "r"(b1))

#define CP16(saddr, gptr) \
    asm volatile("cp.async.cg.shared.global [%0],[%1],16;" :: "r"(saddr), "l"(gptr))
#define CP_COMMIT() asm volatile("cp.async.commit_group;")
#define CP_WAIT0()  asm volatile("cp.async.wait_group 0;")
#define CP_WAIT1()  asm volatile("cp.async.wait_group 1;")

#define RED4(ptr, v) \
    asm volatile("red.global.add.v4.f32 [%0], {%1,%2,%3,%4};" \
                 :: "l"(ptr), "f"((v).x), "f"((v).y), "f"((v).z), "f"((v).w) : "memory")

// ============================================================================
// weight prep (fp16 hi|lo split along k')
// edge: rb = nh*128 + nwl*32 + g*8 + jj -> orig_n = g*64 + nh*32 + nwl*8 + jj
// ============================================================================
__global__ void prep_edge_w(const float* __restrict__ Wih, const float* __restrict__ Whh,
                            __half* __restrict__ W2t) {
    int idx = blockIdx.x * 256 + threadIdx.x;
    int rb = idx >> 7, k = idx & 127;
    int nh = rb >> 7, nwl = (rb >> 5) & 3, g = (rb >> 3) & 3, jj = rb & 7;
    int orig_n = g * 64 + nh * 32 + nwl * 8 + jj;
    float v = (k < 64) ? Wih[k * 256 + orig_n] : Whh[(k - 64) * 256 + orig_n];
    __half hi, lo; split_f16(v, hi, lo);
    W2t[rb * 256 + k] = hi;
    W2t[rb * 256 + 128 + k] = lo;
}

// node: rb = nh*256 + nw*64 + g*16 + jj -> orig_n = g*128 + nh*64 + nw*16 + jj
__global__ void prep_node_w(const float* __restrict__ Wih, const float* __restrict__ Whh,
                            __half* __restrict__ W2t) {
    int idx = blockIdx.x * 256 + threadIdx.x;
    int rb = idx >> 8, k = idx & 255;
    int nh = rb >> 8, nw = (rb >> 6) & 3, g = (rb >> 4) & 3, jj = rb & 15;
    int orig_n = g * 128 + nh * 64 + nw * 16 + jj;
    float v = (k < 128) ? Wih[k * 512 + orig_n] : Whh[(k - 128) * 512 + orig_n];
    __half hi, lo; split_f16(v, hi, lo);
    W2t[rb * 512 + k] = hi;
    W2t[rb * 512 + 256 + k] = lo;
}

// fp32 -> fp16 plane conversion (initial states); n must be multiple of 512
__global__ void cvt_f2h(const float* __restrict__ s, __half* __restrict__ d) {
    size_t i = (size_t)(blockIdx.x * 256 + threadIdx.x) * 2;
    float2 v = *(const float2*)(s + i);
    *(__half2*)(d + i) = __floats2half2_rn(v.x, v.y);
}

// ============================================================================
// Edge LSTM (hidden 64, K=128, 2-term fp16), merged spatial+temporal,
// N-SPLIT grid.y=2. Block = 64 rows x 32 hidden cells (all 4 gates).
// 8 warps (2M x 4N), warp tile m32 x n32. 3 blocks/SM.
// A: single fp16 plane [64][136] (enc computed; h via cp.async from plane).
// B: W2t hi|lo streamed (8 k32 chunks: 4 hi + 4 lo), both vs same A.
// SMEM: A 17408 | Cs_in [64 x 144B] 9216 | inc 512 | 3x Bbuf 10240
// Epilogue: h staged in dead A region (stride 144), c staged IN-PLACE in Cs.
// ============================================================================
#define E_A   0
#define E_CS  17408
#define E_INC 26624
#define E_BUF 27136
#define E_BUFSZ 10240
#define EDGE_SMEM (27136 + 3 * 10240)
#define SE_BLOCKS (EE / 64)

__global__ __launch_bounds__(256, 3) void edge_mma6_kernel(
    const float* __restrict__ x_s, const float* __restrict__ x_t,
    const float* __restrict__ encw_s, const float* __restrict__ encb_s,
    const float* __restrict__ encw_t, const float* __restrict__ encb_t,
    const __half* __restrict__ W2t_s, const __half* __restrict__ W2t_t,
    const float* __restrict__ bias_s, const float* __restrict__ bias_t,
    const __half* __restrict__ hsp_in, __half* __restrict__ hsp_out,
    float* __restrict__ c_s,
    const __half* __restrict__ htp_in, __half* __restrict__ htp_out,
    float* __restrict__ c_t,
    float* __restrict__ agg, const int* __restrict__ inc)
{
    extern __shared__ char sm[];
    const uint32_t sb = smem_u32(sm);
    const int tid = threadIdx.x;
    const int wid = tid >> 5, l = tid & 31;
    const int mw = wid & 1, nwl = wid >> 1;
    const int m0 = mw * 32;
    const int nh = blockIdx.y;

    const bool is_se = (blockIdx.x < SE_BLOCKS);
    const int row0 = (is_se ? blockIdx.x : (blockIdx.x - SE_BLOCKS)) * 64;
    const float* x    = is_se ? x_s : x_t;
    const float* encw = is_se ? encw_s : encw_t;
    const float* encb = is_se ? encb_s : encb_t;
    const __half* W2t = is_se ? W2t_s : W2t_t;
    const float* bias = is_se ? bias_s : bias_t;
    const __half* hInP = is_se ? hsp_in : htp_in;
    __half* hOutP = is_se ? hsp_out : htp_out;
    float* c = is_se ? c_s : c_t;
    float* aggp = is_se ? agg : nullptr;

    const __half* Wb = W2t + (size_t)(nh * 128) * 256;   // this half's rows

    // ---- group 0: B chunk0 + Cs_in slice + inc + h plane (A cols 64..127) ----
    #pragma unroll
    for (int it = 0; it < 2; ++it) {
        int idx = tid + it * 256;                 // 512 = 128r x 4k8
        int r = idx >> 2, k8 = idx & 3;
        CP16(sb + E_BUF + r * 80 + k8 * 16, Wb + (size_t)r * 256 + 0 * 32 + k8 * 8);
    }
    #pragma unroll
    for (int it = 0; it < 2; ++it) {
        int idx = tid + it * 256;                 // 512 = 64r x 8 seg
        int r = idx >> 3, seg = idx & 7;
        CP16(sb + E_CS + r * 144 + seg * 16,
             c + (size_t)(row0 + r) * 64 + nh * 32 + seg * 4);
    }
    #pragma unroll
    for (int it = 0; it < 2; ++it) {
        int idx = tid + it * 256;                 // 512 = 64r x 8 seg (h: 64 fp16)
        int r = idx >> 3, seg = idx & 7;
        CP16(sb + E_A + r * 272 + 128 + seg * 16,
             hInP + (size_t)(row0 + r) * 64 + seg * 8);
    }
    if (is_se && tid < 32)
        CP16(sb + E_INC + tid * 16, inc + 2 * row0 + tid * 4);
    CP_COMMIT();
    // ---- group 1: B chunk1 ----
    #pragma unroll
    for (int it = 0; it < 2; ++it) {
        int idx = tid + it * 256;
        int r = idx >> 2, k8 = idx & 3;
        CP16(sb + E_BUF + E_BUFSZ + r * 80 + k8 * 16, Wb + (size_t)r * 256 + 1 * 32 + k8 * 8);
    }
    CP_COMMIT();

    // ---- stage A enc cols 0..63 (computed, fp16) ----
    #pragma unroll
    for (int it = 0; it < 4; ++it) {
        int idx = tid + it * 256;                 // 1024 = 64r x 16 j4-groups
        int r = idx >> 4, j4 = idx & 15;
        int R = row0 + r;
        float x0 = x[R * 2 + 0], x1 = x[R * 2 + 1];
        int j = j4 * 4;
        #pragma unroll
        for (int e = 0; e < 2; ++e) {
            int cc = j + e * 2;
            float v0 = fmaxf(fmaf(x0, __ldg(&encw[cc]),     fmaf(x1, __ldg(&encw[64 + cc]),     __ldg(&encb[cc]))), 0.f);
            float v1 = fmaxf(fmaf(x0, __ldg(&encw[cc + 1]), fmaf(x1, __ldg(&encw[64 + cc + 1]), __ldg(&encb[cc + 1]))), 0.f);
            *(__half2*)(sm + E_A + r * 272 + cc * 2) = __floats2half2_rn(v0, v1);
        }
    }

    // ---- lane-constant offsets ----
    const int qi = l >> 3, ii = l & 7;
    const uint32_t b_lane = ((qi >= 2 ? 8u : 0u) + (uint32_t)ii) * 80u + (qi & 1) * 16u;
    const uint32_t a_lane = (uint32_t)(l & 15) * 272u + (uint32_t)(l >> 4) * 16u;
    const uint32_t aB = sb + E_A + m0 * 272 + a_lane;
    const uint32_t bWarp = nwl * 2560 + b_lane;     // nwl*32 rows * 80B

    float acc[2][4][4];
    #pragma unroll
    for (int mt = 0; mt < 2; ++mt)
        #pragma unroll
        for (int g = 0; g < 4; ++g)
            #pragma unroll
            for (int e = 0; e < 4; ++e) acc[mt][g][e] = 0.f;

    // ---- mainloop: 8 k32 chunks (B hi 0..3, B lo 4..7; A single plane) ----
    for (int cc = 0; cc < 8; ++cc) {
        if (cc < 7) { CP_WAIT1(); } else { CP_WAIT0(); }
        __syncthreads();

        if (cc + 2 < 8) {
            const int cn2 = cc + 2;
            const int koff = ((cn2 < 4) ? 0 : 128) + (cn2 & 3) * 32;
            const uint32_t dstb = sb + E_BUF + (cn2 % 3) * E_BUFSZ;
            #pragma unroll
            for (int it = 0; it < 2; ++it) {
                int idx = tid + it * 256;
                int r = idx >> 2, k8 = idx & 3;
                CP16(dstb + r * 80 + k8 * 16, Wb + (size_t)r * 256 + koff + k8 * 8);
            }
            CP_COMMIT();
        }

        const uint32_t bufB = sb + E_BUF + (cc % 3) * E_BUFSZ + bWarp;
        const uint32_t acol = (uint32_t)(cc & 3) * 64;

        #pragma unroll
        for (int ks2 = 0; ks2 < 2; ++ks2) {
            uint32_t bb[4][2];
            #pragma unroll
            for (int fg = 0; fg < 2; ++fg) {
                uint32_t r0, r1, r2, r3;
                LDSM4(r0, r1, r2, r3, bufB + fg * 1280 + ks2 * 32);
                bb[fg * 2][0] = r0;     bb[fg * 2][1] = r1;
                bb[fg * 2 + 1][0] = r2; bb[fg * 2 + 1][1] = r3;
            }
            #pragma unroll
            for (int mt = 0; mt < 2; ++mt) {
                uint32_t a0, a1, a2, a3;
                LDSM4(a0, a1, a2, a3, aB + mt * 4352 + acol + ks2 * 32);
                #pragma unroll
                for (int g = 0; g < 4; ++g)
                    MMA_F16(acc[mt][g], a0, a1, a2, a3, bb[g][0], bb[g][1]);
            }
        }
    }

    // ---- epilogue: gates -> h staged in dead A region; c staged in-place ----
    __syncthreads();

    const int jl = nwl * 8 + 2 * (l & 3);          // local col in [0,32)
    const int j0 = nh * 32 + jl;                   // global hidden col
    const int rl_base = m0 + (l >> 2);
    #pragma unroll
    for (int mt = 0; mt < 2; ++mt) {
        #pragma unroll
        for (int rh = 0; rh < 2; ++rh) {
            int rl = rl_base + mt * 16 + rh * 8;
            float i0 = acc[mt][0][rh * 2]     + __ldg(&bias[j0]);
            float i1 = acc[mt][0][rh * 2 + 1] + __ldg(&bias[j0 + 1]);
            float f0 = acc[mt][1][rh * 2]     + __ldg(&bias[64 + j0]);
            float f1 = acc[mt][1][rh * 2 + 1] + __ldg(&bias[64 + j0 + 1]);
            float g0 = acc[mt][2][rh * 2]     + __ldg(&bias[128 + j0]);
            float g1 = acc[mt][2][rh * 2 + 1] + __ldg(&bias[128 + j0 + 1]);
            float o0 = acc[mt][3][rh * 2]     + __ldg(&bias[192 + j0]);
            float o1 = acc[mt][3][rh * 2 + 1] + __ldg(&bias[192 + j0 + 1]);
            float2 cold = *(const float2*)(sm + E_CS + rl * 144 + jl * 4);
            float c0 = sigf(f0) * cold.x + sigf(i0) * tanh_f(g0);
            float c1 = sigf(f1) * cold.y + sigf(i1) * tanh_f(g1);
            float h0 = sigf(o0) * tanh_f(c0);
            float h1 = sigf(o1) * tanh_f(c1);
            *(float2*)(sm + rl * 144 + jl * 4)         = make_float2(h0, h1);
            *(float2*)(sm + E_CS + rl * 144 + jl * 4)  = make_float2(c0, c1);
        }
    }
    __syncthreads();

    // ---- writeback: c fp32, h fp16 plane, agg vector red (32-col slice) ----
    const int* incs = (const int*)(sm + E_INC);
    #pragma unroll
    for (int p = 0; p < 2; ++p) {
        int r = p * 32 + (tid >> 3);
        int j4 = tid & 7;
        int R = row0 + r;
        float4 hv = *(const float4*)(sm + r * 144 + j4 * 16);
        float4 cv = *(const float4*)(sm + E_CS + r * 144 + j4 * 16);
        *(float4*)&c[(size_t)R * 64 + nh * 32 + j4 * 4] = cv;
        __half2 p0 = __floats2half2_rn(hv.x, hv.y);
        __half2 p1 = __floats2half2_rn(hv.z, hv.w);
        uint2 pk = make_uint2(*(uint32_t*)&p0, *(uint32_t*)&p1);
        *(uint2*)&hOutP[(size_t)R * 64 + nh * 32 + j4 * 4] = pk;
        if (aggp) {
            int n0 = incs[2 * r], n1 = incs[2 * r + 1];
            RED4(&aggp[(size_t)n0 * 64 + nh * 32 + j4 * 4], hv);
            RED4(&aggp[(size_t)n1 * 64 + nh * 32 + j4 * 4], hv);
        }
    }
}

// ============================================================================
// emb kernel: enc/emb + hn snapshot into the fp16 plane g_xe.
// Reads temporal h from fp16 plane.
// ============================================================================
#define EMB_SMEM (64 * 132 * 4 + 128 * 64 * 4)

__global__ __launch_bounds__(256) void emb_kernel(
    const float* __restrict__ xn,
    const float* __restrict__ nencw, const float* __restrict__ nencb,
    const float* __restrict__ eew,   const float* __restrict__ eeb,
    const __half* __restrict__ htp,  const float* __restrict__ agg,
    const float* __restrict__ hn,
    __half* __restrict__ xe)
{
    extern __shared__ float smf[];
    float* Asf  = smf;                 // [64][132]
    float* eewS = smf + 64 * 132;      // [128][64]

    const int tid = threadIdx.x;
    const int row0 = blockIdx.x * 64;

    #pragma unroll
    for (int it = 0; it < 16; ++it) {
        int idx = tid + it * 256;
        int r = idx >> 6, j = idx & 63;
        int R = row0 + r;
        Asf[r * 132 + j]      = __half2float(htp[(size_t)R * 64 + j]);
        Asf[r * 132 + 64 + j] = agg[(size_t)R * 64 + j];
    }
    #pragma unroll
    for (int it = 0; it < 8; ++it) {
        int f4 = tid + it * 256;
        *(float4*)&eewS[f4 * 4] = *(const float4*)&eew[f4 * 4];
    }

    // hn snapshot -> plane cols 128..255
    #pragma unroll
    for (int it = 0; it < 16; ++it) {
        int idx = tid + it * 256;
        int r = idx >> 6, jp = idx & 63;
        int R = row0 + r;
        float2 hv = *(const float2*)&hn[(size_t)R * 128 + jp * 2];
        *(__half2*)&xe[(size_t)R * 256 + 128 + jp * 2] = __floats2half2_rn(hv.x, hv.y);
    }
    __syncthreads();

    const int r = tid >> 2, jq = tid & 3;
    const int R = row0 + r;

    // enc cols jq*16..+16
    {
        float xv = xn[R];
        #pragma unroll
        for (int u = 0; u < 8; ++u) {
            int cc = jq * 16 + u * 2;
            float v0 = fmaxf(fmaf(xv, __ldg(&nencw[cc]),     __ldg(&nencb[cc])), 0.f);
            float v1 = fmaxf(fmaf(xv, __ldg(&nencw[cc + 1]), __ldg(&nencb[cc + 1])), 0.f);
            *(__half2*)&xe[(size_t)R * 256 + cc] = __floats2half2_rn(v0, v1);
        }
    }

    // emb cols jq*16..+16
    {
        float accv[16];
        #pragma unroll
        for (int u = 0; u < 16; ++u) accv[u] = __ldg(&eeb[jq * 16 + u]);
        #pragma unroll 4
        for (int k = 0; k < 128; ++k) {
            float a = Asf[r * 132 + k];
            #pragma unroll
            for (int g = 0; g < 4; ++g) {
                float4 w4 = *(const float4*)&eewS[k * 64 + jq * 16 + g * 4];
                accv[g*4+0] = fmaf(a, w4.x, accv[g*4+0]);
                accv[g*4+1] = fmaf(a, w4.y, accv[g*4+1]);
                accv[g*4+2] = fmaf(a, w4.z, accv[g*4+2]);
                accv[g*4+3] = fmaf(a, w4.w, accv[g*4+3]);
            }
        }
        #pragma unroll
        for (int u = 0; u < 8; ++u) {
            float v0 = fmaxf(accv[u * 2], 0.f);
            float v1 = fmaxf(accv[u * 2 + 1], 0.f);
            int cc = 64 + jq * 16 + u * 2;
            *(__half2*)&xe[(size_t)R * 256 + cc] = __floats2half2_rn(v0, v1);
        }
    }
}

// ============================================================================
// Node LSTM GEMM (hidden 128, K=256, 2-term fp16). Grid (NN/64, 2).
// A: single fp16 plane [64][264] via cp.async. B hi|lo streamed (32 k16).
// SMEM: A 33792 | 3x Bbuf 12288. Epilogue staging reuses A + 1KB of dead ring.
// ============================================================================
#define N_A   0
#define N_BUF 33792
#define N_BUFSZ 12288
#define NODE_SMEM (33792 + 3 * 12288)

__global__ __launch_bounds__(256, 2) void node_mma5_kernel(
    const __half* __restrict__ xe,
    const __half* __restrict__ W2t,
    const float* __restrict__ bias,
    const float* __restrict__ outw,  const float* __restrict__ outb,
    float* __restrict__ hn, float* __restrict__ cn,
    float* __restrict__ out)
{
    extern __shared__ char sm[];
    const uint32_t sb = smem_u32(sm);
    const int tid = threadIdx.x;
    const int wid = tid >> 5, l = tid & 31;
    const int mw = wid & 1, nw = wid >> 1;
    const int m0 = mw * 32;
    const int row0 = blockIdx.x * 64;
    const int nh = blockIdx.y;
    const __half* Wb = W2t + (size_t)(nh * 256) * 512;

    // ---- group 0: stage A (256 fp16 cols) ----
    #pragma unroll
    for (int it = 0; it < 8; ++it) {
        int idx = tid + it * 256;   // 2048 = 64r x 32 k8
        int r = idx >> 5, k8 = idx & 31;
        CP16(sb + N_A + r * 528 + k8 * 16, xe + (size_t)(row0 + r) * 256 + k8 * 8);
    }
    CP_COMMIT();

    // ---- groups 1,2: preload B chunks 0,1 (k16 each) ----
    #pragma unroll
    for (int it = 0; it < 2; ++it) {
        int idx = tid + it * 256;
        int r = idx >> 1, k8 = idx & 1;
        CP16(sb + N_BUF + r * 48 + k8 * 16, Wb + (size_t)r * 512 + 0 * 16 + k8 * 8);
    }
    CP_COMMIT();
    #pragma unroll
    for (int it = 0; it < 2; ++it) {
        int idx = tid + it * 256;
        int r = idx >> 1, k8 = idx & 1;
        CP16(sb + N_BUF + N_BUFSZ + r * 48 + k8 * 16, Wb + (size_t)r * 512 + 1 * 16 + k8 * 8);
    }
    CP_COMMIT();

    // ---- cold (cn) register prefetch ----
    float2 cold[2][2][2];
    #pragma unroll
    for (int mt = 0; mt < 2; ++mt)
        #pragma unroll
        for (int rh = 0; rh < 2; ++rh)
            #pragma unroll
            for (int u = 0; u < 2; ++u) {
                int R = row0 + m0 + (l >> 2) + mt * 16 + rh * 8;
                int j0 = nh * 64 + nw * 16 + u * 8 + 2 * (l & 3);
                cold[mt][rh][u] = __ldg((const float2*)&cn[(size_t)R * 128 + j0]);
            }

    const int qi = l >> 3, ii = l & 7;
    const uint32_t b_lane = ((qi >= 2 ? 8u : 0u) + (uint32_t)ii) * 48u + (qi & 1) * 16u;
    const uint32_t a_lane = (uint32_t)(l & 15) * 528u + (uint32_t)(l >> 4) * 16u;
    const uint32_t aB = sb + N_A + m0 * 528 + a_lane;
    const uint32_t bWarp = nw * 3072 + b_lane;

    float acc[2][8][4];
    #pragma unroll
    for (int mt = 0; mt < 2; ++mt)
        #pragma unroll
        for (int nt = 0; nt < 8; ++nt)
            #pragma unroll
            for (int e = 0; e < 4; ++e) acc[mt][nt][e] = 0.f;

    // ---- mainloop: 32 k16 chunks (B hi 0..15, B lo 16..31; A single) ----
    for (int cc = 0; cc < 32; ++cc) {
        if (cc < 31) { CP_WAIT1(); } else { CP_WAIT0(); }
        __syncthreads();

        if (cc + 2 < 32) {
            const int cn2 = cc + 2;
            const uint32_t dstb = sb + N_BUF + (cn2 % 3) * N_BUFSZ;
            #pragma unroll
            for (int it = 0; it < 2; ++it) {
                int idx = tid + it * 256;
                int r = idx >> 1, k8 = idx & 1;
                CP16(dstb + r * 48 + k8 * 16, Wb + (size_t)r * 512 + cn2 * 16 + k8 * 8);
            }
            CP_COMMIT();
        }

        const uint32_t bufB = sb + N_BUF + (cc % 3) * N_BUFSZ + bWarp;
        const uint32_t acol = (uint32_t)(cc & 15) * 32;

        uint32_t bb[8][2];
        #pragma unroll
        for (int fg = 0; fg < 4; ++fg) {
            uint32_t r0, r1, r2, r3;
            LDSM4(r0, r1, r2, r3, bufB + fg * 768);
            bb[fg * 2][0] = r0;     bb[fg * 2][1] = r1;
            bb[fg * 2 + 1][0] = r2; bb[fg * 2 + 1][1] = r3;
        }
        #pragma unroll
        for (int mt = 0; mt < 2; ++mt) {
            uint32_t a0, a1, a2, a3;
            LDSM4(a0, a1, a2, a3, aB + mt * 8448 + acol);
            #pragma unroll
            for (int nt = 0; nt < 8; ++nt)
                MMA_F16(acc[mt][nt], a0, a1, a2, a3, bb[nt][0], bb[nt][1]);
        }
    }

    // ---- epilogue: gates -> staged h/c (272B stride; A + dead ring) ----
    __syncthreads();

    const float ob = (nh == 0 && nw == 0) ? __ldg(outb) : 0.f;
    const int rl_base = m0 + (l >> 2);
    #pragma unroll
    for (int mt = 0; mt < 2; ++mt) {
        #pragma unroll
        for (int rh = 0; rh < 2; ++rh) {
            int rl = rl_base + mt * 16 + rh * 8;
            int R = row0 + rl;
            float po = 0.f;
            #pragma unroll
            for (int u = 0; u < 2; ++u) {
                int j0 = nh * 64 + nw * 16 + u * 8 + 2 * (l & 3);
                int jl = j0 - nh * 64;
                float i0 = acc[mt][u][rh * 2]          + __ldg(&bias[j0]);
                float i1 = acc[mt][u][rh * 2 + 1]      + __ldg(&bias[j0 + 1]);
                float f0 = acc[mt][2 + u][rh * 2]      + __ldg(&bias[128 + j0]);
                float f1 = acc[mt][2 + u][rh * 2 + 1]  + __ldg(&bias[128 + j0 + 1]);
                float g0 = acc[mt][4 + u][rh * 2]      + __ldg(&bias[256 + j0]);
                float g1 = acc[mt][4 + u][rh * 2 + 1]  + __ldg(&bias[256 + j0 + 1]);
                float o0 = acc[mt][6 + u][rh * 2]      + __ldg(&bias[384 + j0]);
                float o1 = acc[mt][6 + u][rh * 2 + 1]  + __ldg(&bias[384 + j0 + 1]);
                float2 cv = cold[mt][rh][u];
                float c0 = sigf(f0) * cv.x + sigf(i0) * tanh_f(g0);
                float c1 = sigf(f1) * cv.y + sigf(i1) * tanh_f(g1);
                float h0 = sigf(o0) * tanh_f(c0);
                float h1 = sigf(o1) * tanh_f(c1);
                *(float2*)(sm + rl * 272 + jl * 4)         = make_float2(h0, h1);
                *(float2*)(sm + 17408 + rl * 272 + jl * 4) = make_float2(c0, c1);
                po = fmaf(h0, __ldg(&outw[j0]), po);
                po = fmaf(h1, __ldg(&outw[j0 + 1]), po);
            }
            po += __shfl_xor_sync(0xffffffffu, po, 1);
            po += __shfl_xor_sync(0xffffffffu, po, 2);
            if ((l & 3) == 0) atomicAdd(&out[R], po + ob);
        }
    }
    __syncthreads();

    #pragma unroll
    for (int p = 0; p < 4; ++p) {
        int r = p * 16 + (tid >> 4);
        int j4 = tid & 15;
        int R = row0 + r;
        float4 hv = *(const float4*)(sm + r * 272 + j4 * 16);
        float4 cv = *(const float4*)(sm + 17408 + r * 272 + j4 * 16);
        *(float4*)&hn[(size_t)R * 128 + nh * 64 + j4 * 4] = hv;
        *(float4*)&cn[(size_t)R * 128 + nh * 64 + j4 * 4] = cv;
    }
}

// ============================================================================
extern "C" void kernel_launch(void* const* d_in, const int* in_sizes, int n_in,
                              void* d_out, int out_size) {
    const float* data_nodes = (const float*)d_in[0];
    const float* data_te    = (const float*)d_in[1];
    const float* data_se    = (const float*)d_in[2];
    const float* h_n0 = (const float*)d_in[3];
    const float* c_n0 = (const float*)d_in[4];
    const float* h_t0 = (const float*)d_in[5];
    const float* c_t0 = (const float*)d_in[6];
    const float* h_s0 = (const float*)d_in[7];
    const float* c_s0 = (const float*)d_in[8];
    const int*   inc  = (const int*)d_in[9];
    const float* t_enc_w = (const float*)d_in[10];
    const float* t_enc_b = (const float*)d_in[11];
    const float* t_Wih   = (const float*)d_in[12];
    const float* t_Whh   = (const float*)d_in[13];
    const float* t_b     = (const float*)d_in[14];
    const float* s_enc_w = (const float*)d_in[15];
    const float* s_enc_b = (const float*)d_in[16];
    const float* s_Wih   = (const float*)d_in[17];
    const float* s_Whh   = (const float*)d_in[18];
    const float* s_b     = (const float*)d_in[19];
    const float* n_enc_w = (const float*)d_in[20];
    const float* n_enc_b = (const float*)d_in[21];
    const float* ee_w    = (const float*)d_in[22];
    const float* ee_b    = (const float*)d_in[23];
    const float* n_Wih   = (const float*)d_in[24];
    const float* n_Whh   = (const float*)d_in[25];
    const float* n_b     = (const float*)d_in[26];
    const float* out_w   = (const float*)d_in[27];
    const float* out_b   = (const float*)d_in[28];
    float* out = (float*)d_out;

    float *cs, *ct, *hn, *cn, *agg2;
    __half *hsp, *htp, *w2t_s, *w2t_t, *w2t_n, *xe;
    cudaGetSymbolAddress((void**)&hsp, g_hsp);
    cudaGetSymbolAddress((void**)&cs,  g_cs);
    cudaGetSymbolAddress((void**)&htp, g_htp);
    cudaGetSymbolAddress((void**)&ct,  g_ct);
    cudaGetSymbolAddress((void**)&hn,  g_hn);
    cudaGetSymbolAddress((void**)&cn,  g_cn);
    cudaGetSymbolAddress((void**)&agg2, g_agg2);
    cudaGetSymbolAddress((void**)&w2t_s, g_w2t_s);
    cudaGetSymbolAddress((void**)&w2t_t, g_w2t_t);
    cudaGetSymbolAddress((void**)&w2t_n, g_w2t_n);
    cudaGetSymbolAddress((void**)&xe, g_xe);

    static bool s_init = false;
    static cudaStream_t s1, s2;
    static cudaEvent_t evRoot, evJ1, evJ2;
    static cudaEvent_t evEdge[SSTEPS], evEmb[SSTEPS];
    if (!s_init) {
        s_init = true;
        cudaStreamCreateWithFlags(&s1, cudaStreamNonBlocking);
        cudaStreamCreateWithFlags(&s2, cudaStreamNonBlocking);
        cudaEventCreateWithFlags(&evRoot, cudaEventDisableTiming);
        cudaEventCreateWithFlags(&evJ1, cudaEventDisableTiming);
        cudaEventCreateWithFlags(&evJ2, cudaEventDisableTiming);
        for (int t = 0; t < SSTEPS; ++t) {
            cudaEventCreateWithFlags(&evEdge[t], cudaEventDisableTiming);
            cudaEventCreateWithFlags(&evEmb[t], cudaEventDisableTiming);
        }
        cudaFuncSetAttribute(edge_mma6_kernel, cudaFuncAttributeMaxDynamicSharedMemorySize, EDGE_SMEM);
        cudaFuncSetAttribute(node_mma5_kernel, cudaFuncAttributeMaxDynamicSharedMemorySize, NODE_SMEM);
        cudaFuncSetAttribute(emb_kernel,       cudaFuncAttributeMaxDynamicSharedMemorySize, EMB_SMEM);
    }

    // ---- prologue on the capture (default) stream ----
    cudaMemcpyAsync(cs, c_s0, (size_t)EE * 64  * 4, cudaMemcpyDeviceToDevice);
    cudaMemcpyAsync(ct, c_t0, (size_t)NN * 64  * 4, cudaMemcpyDeviceToDevice);
    cudaMemcpyAsync(hn, h_n0, (size_t)NN * 128 * 4, cudaMemcpyDeviceToDevice);
    cudaMemcpyAsync(cn, c_n0, (size_t)NN * 128 * 4, cudaMemcpyDeviceToDevice);
    cudaMemsetAsync(out, 0, (size_t)SSTEPS * NN * 4);

    cvt_f2h<<<EE * 64 / 512, 256>>>(h_s0, hsp);        // spatial h plane, buffer 0
    cvt_f2h<<<NN * 64 / 512, 256>>>(h_t0, htp);        // temporal h plane, buffer 0
    prep_edge_w<<<128, 256>>>(s_Wih, s_Whh, w2t_s);
    prep_edge_w<<<128, 256>>>(t_Wih, t_Whh, w2t_t);
    prep_node_w<<<512, 256>>>(n_Wih, n_Whh, w2t_n);

    // ---- fork ----
    cudaEventRecord(evRoot, 0);
    cudaStreamWaitEvent(s1, evRoot, 0);
    cudaStreamWaitEvent(s2, evRoot, 0);

    const int edge_grid_x = SE_BLOCKS + NN / 64;   // 2048 + 512
    const size_t HTB = (size_t)NN * 64;
    const size_t HSB = (size_t)EE * 64;

    for (int t = 0; t < SSTEPS; ++t) {
        float* aggT  = agg2 + (size_t)(t & 1) * HTB;
        __half* htIn  = htp + (size_t)(t % 3) * HTB;
        __half* htOut = htp + (size_t)((t + 1) % 3) * HTB;
        __half* hsIn  = hsp + (size_t)(t & 1) * HSB;
        __half* hsOut = hsp + (size_t)((t + 1) & 1) * HSB;

        if (t >= 2) cudaStreamWaitEvent(s1, evEmb[t - 2], 0);
        cudaMemsetAsync(aggT, 0, HTB * 4, s1);
        edge_mma6_kernel<<<dim3(edge_grid_x, 2), 256, EDGE_SMEM, s1>>>(
            data_se + (size_t)t * EE * 2, data_te + (size_t)t * NN * 2,
            s_enc_w, s_enc_b, t_enc_w, t_enc_b,
            w2t_s, w2t_t, s_b, t_b,
            hsIn, hsOut, cs, htIn, htOut, ct, aggT, inc);
        cudaEventRecord(evEdge[t], s1);

        cudaStreamWaitEvent(s2, evEdge[t], 0);
        emb_kernel<<<NN / 64, 256, EMB_SMEM, s2>>>(
            data_nodes + (size_t)t * NN,
            n_enc_w, n_enc_b, ee_w, ee_b,
            htOut, aggT, hn, xe);
        cudaEventRecord(evEmb[t], s2);
        node_mma5_kernel<<<dim3(NN / 64, 2), 256, NODE_SMEM, s2>>>(
            xe, w2t_n, n_b, out_w, out_b,
            hn, cn, out + (size_t)t * NN);
    }

    // ---- join back to the capture stream ----
    cudaEventRecord(evJ1, s1);
    cudaEventRecord(evJ2, s2);
    cudaStreamWaitEvent(0, evJ1, 0);
    cudaStreamWaitEvent(0, evJ2, 0);
}

// round 15
// speedup vs baseline: 1.6899x; 1.1722x over previous
#include <cuda_runtime.h>
#include <cuda_fp16.h>
#include <cstdint>

#define SSTEPS 16
#define NN 32768
#define EE 131072

// -------- persistent state (device globals; no allocation allowed) --------
__device__ __half g_hsp[(size_t)2 * EE * 64];   // ping-pong spatial h (fp16 plane)
__device__ float  g_cs[(size_t)EE * 64];
__device__ __half g_htp[(size_t)3 * NN * 64];   // triple-buffered temporal h (fp16)
__device__ float  g_ct[(size_t)NN * 64];
__device__ float  g_hn[(size_t)NN * 128];
__device__ float  g_cn[(size_t)NN * 128];
__device__ float  g_agg2[(size_t)2 * NN * 64];  // double-buffered agg

// single-term fp16, gate-interleaved, n-major weights
__device__ __half g_w2t_s[256 * 128];
__device__ __half g_w2t_t[256 * 128];
__device__ __half g_w2t_n[512 * 256];

// node input plane: [enc(64) | emb(64) | hn_snapshot(128)] fp16
__device__ __half g_xe[(size_t)NN * 256];

__device__ __forceinline__ float sigf(float x)   { return 1.f / (1.f + __expf(-x)); }
__device__ __forceinline__ float tanh_f(float x) { return 2.f / (1.f + __expf(-2.f * x)) - 1.f; }

__device__ __forceinline__ uint32_t smem_u32(const void* p) {
    return (uint32_t)__cvta_generic_to_shared(p);
}

#define LDSM4(r0, r1, r2, r3, addr) \
    asm volatile("ldmatrix.sync.aligned.m8n8.x4.shared.b16 {%0,%1,%2,%3},[%4];" \
                 : "=r"(r0), "=r"(r1), "=r"(r2), "=r"(r3) : "r"(addr))

#define MMA_F16(D, a0, a1, a2, a3, b0, b1) \
    asm volatile("mma.sync.aligned.m16n8k16.row.col.f32.f16.f16.f32 " \
                 "{%0,%1,%2,%3},{%4,%5,%6,%7},{%8,%9},{%0,%1,%2,%3};" \
                 : "+f"(D[0]), "+f"(D[1]), "+f"(D[2]), "+f"(D[3]) \
                 : "r"(a0), "r"(a1), "r"(a2), "r"(a3), "r"(b0), "r"(b1))

#define CP16(saddr, gptr) \
    asm volatile("cp.async.cg.shared.global [%0],[%1],16;" :: "r"(saddr), "l"(gptr))
#define CP_COMMIT() asm volatile("cp.async.commit_group;")
#define CP_WAIT0()  asm volatile("cp.async.wait_group 0;")
#define CP_WAIT1()  asm volatile("cp.async.wait_group 1;")

#define RED4(ptr, v) \
    asm volatile("red.global.add.v4.f32 [%0], {%1,%2,%3,%4};" \
                 :: "l"(ptr), "f"((v).x), "f"((v).y), "f"((v).z), "f"((v).w) : "memory")

// ============================================================================
// weight prep (single-term fp16)
// edge: rb = nh*128 + nwl*32 + g*8 + jj -> orig_n = g*64 + nh*32 + nwl*8 + jj
// ============================================================================
__global__ void prep_edge_w(const float* __restrict__ Wih, const float* __restrict__ Whh,
                            __half* __restrict__ W2t) {
    int idx = blockIdx.x * 256 + threadIdx.x;   // 256 rb * 128 k
    int rb = idx >> 7, k = idx & 127;
    int nh = rb >> 7, nwl = (rb >> 5) & 3, g = (rb >> 3) & 3, jj = rb & 7;
    int orig_n = g * 64 + nh * 32 + nwl * 8 + jj;
    float v = (k < 64) ? Wih[k * 256 + orig_n] : Whh[(k - 64) * 256 + orig_n];
    W2t[rb * 128 + k] = __float2half(v);
}

// node: rb = nh*256 + nw*64 + g*16 + jj -> orig_n = g*128 + nh*64 + nw*16 + jj
__global__ void prep_node_w(const float* __restrict__ Wih, const float* __restrict__ Whh,
                            __half* __restrict__ W2t) {
    int idx = blockIdx.x * 256 + threadIdx.x;   // 512 rb * 256 k
    int rb = idx >> 8, k = idx & 255;
    int nh = rb >> 8, nw = (rb >> 6) & 3, g = (rb >> 4) & 3, jj = rb & 15;
    int orig_n = g * 128 + nh * 64 + nw * 16 + jj;
    float v = (k < 128) ? Wih[k * 512 + orig_n] : Whh[(k - 128) * 512 + orig_n];
    W2t[rb * 256 + k] = __float2half(v);
}

// fp32 -> fp16 plane conversion (initial states); n must be multiple of 512
__global__ void cvt_f2h(const float* __restrict__ s, __half* __restrict__ d) {
    size_t i = (size_t)(blockIdx.x * 256 + threadIdx.x) * 2;
    float2 v = *(const float2*)(s + i);
    *(__half2*)(d + i) = __floats2half2_rn(v.x, v.y);
}

// ============================================================================
// Edge LSTM (hidden 64, K=128, single-term fp16), merged spatial+temporal,
// N-SPLIT grid.y=2. Block = 64 rows x 32 hidden cells (all 4 gates).
// 8 warps (2M x 4N), warp tile m32 x n32. 3 blocks/SM.
// A: single fp16 plane [64][136]. B: 4 k32 chunks streamed.
// SMEM: A 17408 | Cs_in [64 x 144B] 9216 | inc 512 | 3x Bbuf 10240
// ============================================================================
#define E_A   0
#define E_CS  17408
#define E_INC 26624
#define E_BUF 27136
#define E_BUFSZ 10240
#define EDGE_SMEM (27136 + 3 * 10240)
#define SE_BLOCKS (EE / 64)

__global__ __launch_bounds__(256, 3) void edge_mma7_kernel(
    const float* __restrict__ x_s, const float* __restrict__ x_t,
    const float* __restrict__ encw_s, const float* __restrict__ encb_s,
    const float* __restrict__ encw_t, const float* __restrict__ encb_t,
    const __half* __restrict__ W2t_s, const __half* __restrict__ W2t_t,
    const float* __restrict__ bias_s, const float* __restrict__ bias_t,
    const __half* __restrict__ hsp_in, __half* __restrict__ hsp_out,
    float* __restrict__ c_s,
    const __half* __restrict__ htp_in, __half* __restrict__ htp_out,
    float* __restrict__ c_t,
    float* __restrict__ agg, const int* __restrict__ inc)
{
    extern __shared__ char sm[];
    const uint32_t sb = smem_u32(sm);
    const int tid = threadIdx.x;
    const int wid = tid >> 5, l = tid & 31;
    const int mw = wid & 1, nwl = wid >> 1;
    const int m0 = mw * 32;
    const int nh = blockIdx.y;

    const bool is_se = (blockIdx.x < SE_BLOCKS);
    const int row0 = (is_se ? blockIdx.x : (blockIdx.x - SE_BLOCKS)) * 64;
    const float* x    = is_se ? x_s : x_t;
    const float* encw = is_se ? encw_s : encw_t;
    const float* encb = is_se ? encb_s : encb_t;
    const __half* W2t = is_se ? W2t_s : W2t_t;
    const float* bias = is_se ? bias_s : bias_t;
    const __half* hInP = is_se ? hsp_in : htp_in;
    __half* hOutP = is_se ? hsp_out : htp_out;
    float* c = is_se ? c_s : c_t;
    float* aggp = is_se ? agg : nullptr;

    const __half* Wb = W2t + (size_t)(nh * 128) * 128;   // this half's rows

    // ---- group 0: B chunk0 + Cs_in slice + inc + h plane (A cols 64..127) ----
    #pragma unroll
    for (int it = 0; it < 2; ++it) {
        int idx = tid + it * 256;                 // 512 = 128r x 4k8
        int r = idx >> 2, k8 = idx & 3;
        CP16(sb + E_BUF + r * 80 + k8 * 16, Wb + (size_t)r * 128 + 0 * 32 + k8 * 8);
    }
    #pragma unroll
    for (int it = 0; it < 2; ++it) {
        int idx = tid + it * 256;                 // 512 = 64r x 8 seg
        int r = idx >> 3, seg = idx & 7;
        CP16(sb + E_CS + r * 144 + seg * 16,
             c + (size_t)(row0 + r) * 64 + nh * 32 + seg * 4);
    }
    #pragma unroll
    for (int it = 0; it < 2; ++it) {
        int idx = tid + it * 256;                 // 512 = 64r x 8 seg (h: 64 fp16)
        int r = idx >> 3, seg = idx & 7;
        CP16(sb + E_A + r * 272 + 128 + seg * 16,
             hInP + (size_t)(row0 + r) * 64 + seg * 8);
    }
    if (is_se && tid < 32)
        CP16(sb + E_INC + tid * 16, inc + 2 * row0 + tid * 4);
    CP_COMMIT();
    // ---- group 1: B chunk1 ----
    #pragma unroll
    for (int it = 0; it < 2; ++it) {
        int idx = tid + it * 256;
        int r = idx >> 2, k8 = idx & 3;
        CP16(sb + E_BUF + E_BUFSZ + r * 80 + k8 * 16, Wb + (size_t)r * 128 + 1 * 32 + k8 * 8);
    }
    CP_COMMIT();

    // ---- stage A enc cols 0..63 (computed, fp16) ----
    #pragma unroll
    for (int it = 0; it < 4; ++it) {
        int idx = tid + it * 256;                 // 1024 = 64r x 16 j4-groups
        int r = idx >> 4, j4 = idx & 15;
        int R = row0 + r;
        float x0 = x[R * 2 + 0], x1 = x[R * 2 + 1];
        int j = j4 * 4;
        #pragma unroll
        for (int e = 0; e < 2; ++e) {
            int cc = j + e * 2;
            float v0 = fmaxf(fmaf(x0, __ldg(&encw[cc]),     fmaf(x1, __ldg(&encw[64 + cc]),     __ldg(&encb[cc]))), 0.f);
            float v1 = fmaxf(fmaf(x0, __ldg(&encw[cc + 1]), fmaf(x1, __ldg(&encw[64 + cc + 1]), __ldg(&encb[cc + 1]))), 0.f);
            *(__half2*)(sm + E_A + r * 272 + cc * 2) = __floats2half2_rn(v0, v1);
        }
    }

    // ---- lane-constant offsets ----
    const int qi = l >> 3, ii = l & 7;
    const uint32_t b_lane = ((qi >= 2 ? 8u : 0u) + (uint32_t)ii) * 80u + (qi & 1) * 16u;
    const uint32_t a_lane = (uint32_t)(l & 15) * 272u + (uint32_t)(l >> 4) * 16u;
    const uint32_t aB = sb + E_A + m0 * 272 + a_lane;
    const uint32_t bWarp = nwl * 2560 + b_lane;     // nwl*32 rows * 80B

    float acc[2][4][4];
    #pragma unroll
    for (int mt = 0; mt < 2; ++mt)
        #pragma unroll
        for (int g = 0; g < 4; ++g)
            #pragma unroll
            for (int e = 0; e < 4; ++e) acc[mt][g][e] = 0.f;

    // ---- mainloop: 4 k32 chunks ----
    for (int cc = 0; cc < 4; ++cc) {
        if (cc < 3) { CP_WAIT1(); } else { CP_WAIT0(); }
        __syncthreads();

        if (cc + 2 < 4) {
            const int cn2 = cc + 2;
            const uint32_t dstb = sb + E_BUF + (cn2 % 3) * E_BUFSZ;
            #pragma unroll
            for (int it = 0; it < 2; ++it) {
                int idx = tid + it * 256;
                int r = idx >> 2, k8 = idx & 3;
                CP16(dstb + r * 80 + k8 * 16, Wb + (size_t)r * 128 + cn2 * 32 + k8 * 8);
            }
            CP_COMMIT();
        }

        const uint32_t bufB = sb + E_BUF + (cc % 3) * E_BUFSZ + bWarp;
        const uint32_t acol = (uint32_t)cc * 64;

        #pragma unroll
        for (int ks2 = 0; ks2 < 2; ++ks2) {
            uint32_t bb[4][2];
            #pragma unroll
            for (int fg = 0; fg < 2; ++fg) {
                uint32_t r0, r1, r2, r3;
                LDSM4(r0, r1, r2, r3, bufB + fg * 1280 + ks2 * 32);
                bb[fg * 2][0] = r0;     bb[fg * 2][1] = r1;
                bb[fg * 2 + 1][0] = r2; bb[fg * 2 + 1][1] = r3;
            }
            #pragma unroll
            for (int mt = 0; mt < 2; ++mt) {
                uint32_t a0, a1, a2, a3;
                LDSM4(a0, a1, a2, a3, aB + mt * 4352 + acol + ks2 * 32);
                #pragma unroll
                for (int g = 0; g < 4; ++g)
                    MMA_F16(acc[mt][g], a0, a1, a2, a3, bb[g][0], bb[g][1]);
            }
        }
    }

    // ---- epilogue: gates -> h staged in dead A region; c staged in-place ----
    __syncthreads();

    const int jl = nwl * 8 + 2 * (l & 3);          // local col in [0,32)
    const int j0 = nh * 32 + jl;                   // global hidden col
    const int rl_base = m0 + (l >> 2);
    #pragma unroll
    for (int mt = 0; mt < 2; ++mt) {
        #pragma unroll
        for (int rh = 0; rh < 2; ++rh) {
            int rl = rl_base + mt * 16 + rh * 8;
            float i0 = acc[mt][0][rh * 2]     + __ldg(&bias[j0]);
            float i1 = acc[mt][0][rh * 2 + 1] + __ldg(&bias[j0 + 1]);
            float f0 = acc[mt][1][rh * 2]     + __ldg(&bias[64 + j0]);
            float f1 = acc[mt][1][rh * 2 + 1] + __ldg(&bias[64 + j0 + 1]);
            float g0 = acc[mt][2][rh * 2]     + __ldg(&bias[128 + j0]);
            float g1 = acc[mt][2][rh * 2 + 1] + __ldg(&bias[128 + j0 + 1]);
            float o0 = acc[mt][3][rh * 2]     + __ldg(&bias[192 + j0]);
            float o1 = acc[mt][3][rh * 2 + 1] + __ldg(&bias[192 + j0 + 1]);
            float2 cold = *(const float2*)(sm + E_CS + rl * 144 + jl * 4);
            float c0 = sigf(f0) * cold.x + sigf(i0) * tanh_f(g0);
            float c1 = sigf(f1) * cold.y + sigf(i1) * tanh_f(g1);
            float h0 = sigf(o0) * tanh_f(c0);
            float h1 = sigf(o1) * tanh_f(c1);
            *(float2*)(sm + rl * 144 + jl * 4)         = make_float2(h0, h1);
            *(float2*)(sm + E_CS + rl * 144 + jl * 4)  = make_float2(c0, c1);
        }
    }
    __syncthreads();

    // ---- writeback: c fp32, h fp16 plane, agg vector red (32-col slice) ----
    const int* incs = (const int*)(sm + E_INC);
    #pragma unroll
    for (int p = 0; p < 2; ++p) {
        int r = p * 32 + (tid >> 3);
        int j4 = tid & 7;
        int R = row0 + r;
        float4 hv = *(const float4*)(sm + r * 144 + j4 * 16);
        float4 cv = *(const float4*)(sm + E_CS + r * 144 + j4 * 16);
        *(float4*)&c[(size_t)R * 64 + nh * 32 + j4 * 4] = cv;
        __half2 p0 = __floats2half2_rn(hv.x, hv.y);
        __half2 p1 = __floats2half2_rn(hv.z, hv.w);
        uint2 pk = make_uint2(*(uint32_t*)&p0, *(uint32_t*)&p1);
        *(uint2*)&hOutP[(size_t)R * 64 + nh * 32 + j4 * 4] = pk;
        if (aggp) {
            int n0 = incs[2 * r], n1 = incs[2 * r + 1];
            RED4(&aggp[(size_t)n0 * 64 + nh * 32 + j4 * 4], hv);
            RED4(&aggp[(size_t)n1 * 64 + nh * 32 + j4 * 4], hv);
        }
    }
}

// ============================================================================
// emb kernel: enc/emb + hn snapshot into the fp16 plane g_xe.
// ============================================================================
#define EMB_SMEM (64 * 132 * 4 + 128 * 64 * 4)

__global__ __launch_bounds__(256) void emb_kernel(
    const float* __restrict__ xn,
    const float* __restrict__ nencw, const float* __restrict__ nencb,
    const float* __restrict__ eew,   const float* __restrict__ eeb,
    const __half* __restrict__ htp,  const float* __restrict__ agg,
    const float* __restrict__ hn,
    __half* __restrict__ xe)
{
    extern __shared__ float smf[];
    float* Asf  = smf;                 // [64][132]
    float* eewS = smf + 64 * 132;      // [128][64]

    const int tid = threadIdx.x;
    const int row0 = blockIdx.x * 64;

    #pragma unroll
    for (int it = 0; it < 16; ++it) {
        int idx = tid + it * 256;
        int r = idx >> 6, j = idx & 63;
        int R = row0 + r;
        Asf[r * 132 + j]      = __half2float(htp[(size_t)R * 64 + j]);
        Asf[r * 132 + 64 + j] = agg[(size_t)R * 64 + j];
    }
    #pragma unroll
    for (int it = 0; it < 8; ++it) {
        int f4 = tid + it * 256;
        *(float4*)&eewS[f4 * 4] = *(const float4*)&eew[f4 * 4];
    }

    // hn snapshot -> plane cols 128..255
    #pragma unroll
    for (int it = 0; it < 16; ++it) {
        int idx = tid + it * 256;
        int r = idx >> 6, jp = idx & 63;
        int R = row0 + r;
        float2 hv = *(const float2*)&hn[(size_t)R * 128 + jp * 2];
        *(__half2*)&xe[(size_t)R * 256 + 128 + jp * 2] = __floats2half2_rn(hv.x, hv.y);
    }
    __syncthreads();

    const int r = tid >> 2, jq = tid & 3;
    const int R = row0 + r;

    // enc cols jq*16..+16
    {
        float xv = xn[R];
        #pragma unroll
        for (int u = 0; u < 8; ++u) {
            int cc = jq * 16 + u * 2;
            float v0 = fmaxf(fmaf(xv, __ldg(&nencw[cc]),     __ldg(&nencb[cc])), 0.f);
            float v1 = fmaxf(fmaf(xv, __ldg(&nencw[cc + 1]), __ldg(&nencb[cc + 1])), 0.f);
            *(__half2*)&xe[(size_t)R * 256 + cc] = __floats2half2_rn(v0, v1);
        }
    }

    // emb cols jq*16..+16
    {
        float accv[16];
        #pragma unroll
        for (int u = 0; u < 16; ++u) accv[u] = __ldg(&eeb[jq * 16 + u]);
        #pragma unroll 4
        for (int k = 0; k < 128; ++k) {
            float a = Asf[r * 132 + k];
            #pragma unroll
            for (int g = 0; g < 4; ++g) {
                float4 w4 = *(const float4*)&eewS[k * 64 + jq * 16 + g * 4];
                accv[g*4+0] = fmaf(a, w4.x, accv[g*4+0]);
                accv[g*4+1] = fmaf(a, w4.y, accv[g*4+1]);
                accv[g*4+2] = fmaf(a, w4.z, accv[g*4+2]);
                accv[g*4+3] = fmaf(a, w4.w, accv[g*4+3]);
            }
        }
        #pragma unroll
        for (int u = 0; u < 8; ++u) {
            float v0 = fmaxf(accv[u * 2], 0.f);
            float v1 = fmaxf(accv[u * 2 + 1], 0.f);
            int cc = 64 + jq * 16 + u * 2;
            *(__half2*)&xe[(size_t)R * 256 + cc] = __floats2half2_rn(v0, v1);
        }
    }
}

// ============================================================================
// Node LSTM GEMM (hidden 128, K=256, single-term fp16). Grid (NN/64, 2).
// A: single fp16 plane [64][264] via cp.async. B: 16 k16 chunks streamed.
// SMEM: A 33792 | 3x Bbuf 12288.
// ============================================================================
#define N_A   0
#define N_BUF 33792
#define N_BUFSZ 12288
#define NODE_SMEM (33792 + 3 * 12288)

__global__ __launch_bounds__(256, 2) void node_mma6_kernel(
    const __half* __restrict__ xe,
    const __half* __restrict__ W2t,
    const float* __restrict__ bias,
    const float* __restrict__ outw,  const float* __restrict__ outb,
    float* __restrict__ hn, float* __restrict__ cn,
    float* __restrict__ out)
{
    extern __shared__ char sm[];
    const uint32_t sb = smem_u32(sm);
    const int tid = threadIdx.x;
    const int wid = tid >> 5, l = tid & 31;
    const int mw = wid & 1, nw = wid >> 1;
    const int m0 = mw * 32;
    const int row0 = blockIdx.x * 64;
    const int nh = blockIdx.y;
    const __half* Wb = W2t + (size_t)(nh * 256) * 256;

    // ---- group 0: stage A (256 fp16 cols) ----
    #pragma unroll
    for (int it = 0; it < 8; ++it) {
        int idx = tid + it * 256;   // 2048 = 64r x 32 k8
        int r = idx >> 5, k8 = idx & 31;
        CP16(sb + N_A + r * 528 + k8 * 16, xe + (size_t)(row0 + r) * 256 + k8 * 8);
    }
    CP_COMMIT();

    // ---- groups 1,2: preload B chunks 0,1 (k16 each) ----
    #pragma unroll
    for (int it = 0; it < 2; ++it) {
        int idx = tid + it * 256;
        int r = idx >> 1, k8 = idx & 1;
        CP16(sb + N_BUF + r * 48 + k8 * 16, Wb + (size_t)r * 256 + 0 * 16 + k8 * 8);
    }
    CP_COMMIT();
    #pragma unroll
    for (int it = 0; it < 2; ++it) {
        int idx = tid + it * 256;
        int r = idx >> 1, k8 = idx & 1;
        CP16(sb + N_BUF + N_BUFSZ + r * 48 + k8 * 16, Wb + (size_t)r * 256 + 1 * 16 + k8 * 8);
    }
    CP_COMMIT();

    // ---- cold (cn) register prefetch ----
    float2 cold[2][2][2];
    #pragma unroll
    for (int mt = 0; mt < 2; ++mt)
        #pragma unroll
        for (int rh = 0; rh < 2; ++rh)
            #pragma unroll
            for (int u = 0; u < 2; ++u) {
                int R = row0 + m0 + (l >> 2) + mt * 16 + rh * 8;
                int j0 = nh * 64 + nw * 16 + u * 8 + 2 * (l & 3);
                cold[mt][rh][u] = __ldg((const float2*)&cn[(size_t)R * 128 + j0]);
            }

    const int qi = l >> 3, ii = l & 7;
    const uint32_t b_lane = ((qi >= 2 ? 8u : 0u) + (uint32_t)ii) * 48u + (qi & 1) * 16u;
    const uint32_t a_lane = (uint32_t)(l & 15) * 528u + (uint32_t)(l >> 4) * 16u;
    const uint32_t aB = sb + N_A + m0 * 528 + a_lane;
    const uint32_t bWarp = nw * 3072 + b_lane;

    float acc[2][8][4];
    #pragma unroll
    for (int mt = 0; mt < 2; ++mt)
        #pragma unroll
        for (int nt = 0; nt < 8; ++nt)
            #pragma unroll
            for (int e = 0; e < 4; ++e) acc[mt][nt][e] = 0.f;

    // ---- mainloop: 16 k16 chunks ----
    for (int cc = 0; cc < 16; ++cc) {
        if (cc < 15) { CP_WAIT1(); } else { CP_WAIT0(); }
        __syncthreads();

        if (cc + 2 < 16) {
            const int cn2 = cc + 2;
            const uint32_t dstb = sb + N_BUF + (cn2 % 3) * N_BUFSZ;
            #pragma unroll
            for (int it = 0; it < 2; ++it) {
                int idx = tid + it * 256;
                int r = idx >> 1, k8 = idx & 1;
                CP16(dstb + r * 48 + k8 * 16, Wb + (size_t)r * 256 + cn2 * 16 + k8 * 8);
            }
            CP_COMMIT();
        }

        const uint32_t bufB = sb + N_BUF + (cc % 3) * N_BUFSZ + bWarp;
        const uint32_t acol = (uint32_t)cc * 32;

        uint32_t bb[8][2];
        #pragma unroll
        for (int fg = 0; fg < 4; ++fg) {
            uint32_t r0, r1, r2, r3;
            LDSM4(r0, r1, r2, r3, bufB + fg * 768);
            bb[fg * 2][0] = r0;     bb[fg * 2][1] = r1;
            bb[fg * 2 + 1][0] = r2; bb[fg * 2 + 1][1] = r3;
        }
        #pragma unroll
        for (int mt = 0; mt < 2; ++mt) {
            uint32_t a0, a1, a2, a3;
            LDSM4(a0, a1, a2, a3, aB + mt * 8448 + acol);
            #pragma unroll
            for (int nt = 0; nt < 8; ++nt)
                MMA_F16(acc[mt][nt], a0, a1, a2, a3, bb[nt][0], bb[nt][1]);
        }
    }

    // ---- epilogue: gates -> staged h/c (272B stride; A + dead ring) ----
    __syncthreads();

    const float ob = (nh == 0 && nw == 0) ? __ldg(outb) : 0.f;
    const int rl_base = m0 + (l >> 2);
    #pragma unroll
    for (int mt = 0; mt < 2; ++mt) {
        #pragma unroll
        for (int rh = 0; rh < 2; ++rh) {
            int rl = rl_base + mt * 16 + rh * 8;
            int R = row0 + rl;
            float po = 0.f;
            #pragma unroll
            for (int u = 0; u < 2; ++u) {
                int j0 = nh * 64 + nw * 16 + u * 8 + 2 * (l & 3);
                int jl = j0 - nh * 64;
                float i0 = acc[mt][u][rh * 2]          + __ldg(&bias[j0]);
                float i1 = acc[mt][u][rh * 2 + 1]      + __ldg(&bias[j0 + 1]);
                float f0 = acc[mt][2 + u][rh * 2]      + __ldg(&bias[128 + j0]);
                float f1 = acc[mt][2 + u][rh * 2 + 1]  + __ldg(&bias[128 + j0 + 1]);
                float g0 = acc[mt][4 + u][rh * 2]      + __ldg(&bias[256 + j0]);
                float g1 = acc[mt][4 + u][rh * 2 + 1]  + __ldg(&bias[256 + j0 + 1]);
                float o0 = acc[mt][6 + u][rh * 2]      + __ldg(&bias[384 + j0]);
                float o1 = acc[mt][6 + u][rh * 2 + 1]  + __ldg(&bias[384 + j0 + 1]);
                float2 cv = cold[mt][rh][u];
                float c0 = sigf(f0) * cv.x + sigf(i0) * tanh_f(g0);
                float c1 = sigf(f1) * cv.y + sigf(i1) * tanh_f(g1);
                float h0 = sigf(o0) * tanh_f(c0);
                float h1 = sigf(o1) * tanh_f(c1);
                *(float2*)(sm + rl * 272 + jl * 4)         = make_float2(h0, h1);
                *(float2*)(sm + 17408 + rl * 272 + jl * 4) = make_float2(c0, c1);
                po = fmaf(h0, __ldg(&outw[j0]), po);
                po = fmaf(h1, __ldg(&outw[j0 + 1]), po);
            }
            po += __shfl_xor_sync(0xffffffffu, po, 1);
            po += __shfl_xor_sync(0xffffffffu, po, 2);
            if ((l & 3) == 0) atomicAdd(&out[R], po + ob);
        }
    }
    __syncthreads();

    #pragma unroll
    for (int p = 0; p < 4; ++p) {
        int r = p * 16 + (tid >> 4);
        int j4 = tid & 15;
        int R = row0 + r;
        float4 hv = *(const float4*)(sm + r * 272 + j4 * 16);
        float4 cv = *(const float4*)(sm + 17408 + r * 272 + j4 * 16);
        *(float4*)&hn[(size_t)R * 128 + nh * 64 + j4 * 4] = hv;
        *(float4*)&cn[(size_t)R * 128 + nh * 64 + j4 * 4] = cv;
    }
}

// ============================================================================
extern "C" void kernel_launch(void* const* d_in, const int* in_sizes, int n_in,
                              void* d_out, int out_size) {
    const float* data_nodes = (const float*)d_in[0];
    const float* data_te    = (const float*)d_in[1];
    const float* data_se    = (const float*)d_in[2];
    const float* h_n0 = (const float*)d_in[3];
    const float* c_n0 = (const float*)d_in[4];
    const float* h_t0 = (const float*)d_in[5];
    const float* c_t0 = (const float*)d_in[6];
    const float* h_s0 = (const float*)d_in[7];
    const float* c_s0 = (const float*)d_in[8];
    const int*   inc  = (const int*)d_in[9];
    const float* t_enc_w = (const float*)d_in[10];
    const float* t_enc_b = (const float*)d_in[11];
    const float* t_Wih   = (const float*)d_in[12];
    const float* t_Whh   = (const float*)d_in[13];
    const float* t_b     = (const float*)d_in[14];
    const float* s_enc_w = (const float*)d_in[15];
    const float* s_enc_b = (const float*)d_in[16];
    const float* s_Wih   = (const float*)d_in[17];
    const float* s_Whh   = (const float*)d_in[18];
    const float* s_b     = (const float*)d_in[19];
    const float* n_enc_w = (const float*)d_in[20];
    const float* n_enc_b = (const float*)d_in[21];
    const float* ee_w    = (const float*)d_in[22];
    const float* ee_b    = (const float*)d_in[23];
    const float* n_Wih   = (const float*)d_in[24];
    const float* n_Whh   = (const float*)d_in[25];
    const float* n_b     = (const float*)d_in[26];
    const float* out_w   = (const float*)d_in[27];
    const float* out_b   = (const float*)d_in[28];
    float* out = (float*)d_out;

    float *cs, *ct, *hn, *cn, *agg2;
    __half *hsp, *htp, *w2t_s, *w2t_t, *w2t_n, *xe;
    cudaGetSymbolAddress((void**)&hsp, g_hsp);
    cudaGetSymbolAddress((void**)&cs,  g_cs);
    cudaGetSymbolAddress((void**)&htp, g_htp);
    cudaGetSymbolAddress((void**)&ct,  g_ct);
    cudaGetSymbolAddress((void**)&hn,  g_hn);
    cudaGetSymbolAddress((void**)&cn,  g_cn);
    cudaGetSymbolAddress((void**)&agg2, g_agg2);
    cudaGetSymbolAddress((void**)&w2t_s, g_w2t_s);
    cudaGetSymbolAddress((void**)&w2t_t, g_w2t_t);
    cudaGetSymbolAddress((void**)&w2t_n, g_w2t_n);
    cudaGetSymbolAddress((void**)&xe, g_xe);

    static bool s_init = false;
    static cudaStream_t s1, s2;
    static cudaEvent_t evRoot, evJ1, evJ2;
    static cudaEvent_t evEdge[SSTEPS], evEmb[SSTEPS];
    if (!s_init) {
        s_init = true;
        cudaStreamCreateWithFlags(&s1, cudaStreamNonBlocking);
        cudaStreamCreateWithFlags(&s2, cudaStreamNonBlocking);
        cudaEventCreateWithFlags(&evRoot, cudaEventDisableTiming);
        cudaEventCreateWithFlags(&evJ1, cudaEventDisableTiming);
        cudaEventCreateWithFlags(&evJ2, cudaEventDisableTiming);
        for (int t = 0; t < SSTEPS; ++t) {
            cudaEventCreateWithFlags(&evEdge[t], cudaEventDisableTiming);
            cudaEventCreateWithFlags(&evEmb[t], cudaEventDisableTiming);
        }
        cudaFuncSetAttribute(edge_mma7_kernel, cudaFuncAttributeMaxDynamicSharedMemorySize, EDGE_SMEM);
        cudaFuncSetAttribute(node_mma6_kernel, cudaFuncAttributeMaxDynamicSharedMemorySize, NODE_SMEM);
        cudaFuncSetAttribute(emb_kernel,       cudaFuncAttributeMaxDynamicSharedMemorySize, EMB_SMEM);
    }

    // ---- prologue on the capture (default) stream ----
    cudaMemcpyAsync(cs, c_s0, (size_t)EE * 64  * 4, cudaMemcpyDeviceToDevice);
    cudaMemcpyAsync(ct, c_t0, (size_t)NN * 64  * 4, cudaMemcpyDeviceToDevice);
    cudaMemcpyAsync(hn, h_n0, (size_t)NN * 128 * 4, cudaMemcpyDeviceToDevice);
    cudaMemcpyAsync(cn, c_n0, (size_t)NN * 128 * 4, cudaMemcpyDeviceToDevice);
    cudaMemsetAsync(out, 0, (size_t)SSTEPS * NN * 4);

    cvt_f2h<<<EE * 64 / 512, 256>>>(h_s0, hsp);        // spatial h plane, buffer 0
    cvt_f2h<<<NN * 64 / 512, 256>>>(h_t0, htp);        // temporal h plane, buffer 0
    prep_edge_w<<<128, 256>>>(s_Wih, s_Whh, w2t_s);
    prep_edge_w<<<128, 256>>>(t_Wih, t_Whh, w2t_t);
    prep_node_w<<<512, 256>>>(n_Wih, n_Whh, w2t_n);

    // ---- fork ----
    cudaEventRecord(evRoot, 0);
    cudaStreamWaitEvent(s1, evRoot, 0);
    cudaStreamWaitEvent(s2, evRoot, 0);

    const int edge_grid_x = SE_BLOCKS + NN / 64;   // 2048 + 512
    const size_t HTB = (size_t)NN * 64;
    const size_t HSB = (size_t)EE * 64;

    for (int t = 0; t < SSTEPS; ++t) {
        float* aggT  = agg2 + (size_t)(t & 1) * HTB;
        __half* htIn  = htp + (size_t)(t % 3) * HTB;
        __half* htOut = htp + (size_t)((t + 1) % 3) * HTB;
        __half* hsIn  = hsp + (size_t)(t & 1) * HSB;
        __half* hsOut = hsp + (size_t)((t + 1) & 1) * HSB;

        if (t >= 2) cudaStreamWaitEvent(s1, evEmb[t - 2], 0);
        cudaMemsetAsync(aggT, 0, HTB * 4, s1);
        edge_mma7_kernel<<<dim3(edge_grid_x, 2), 256, EDGE_SMEM, s1>>>(
            data_se + (size_t)t * EE * 2, data_te + (size_t)t * NN * 2,
            s_enc_w, s_enc_b, t_enc_w, t_enc_b,
            w2t_s, w2t_t, s_b, t_b,
            hsIn, hsOut, cs, htIn, htOut, ct, aggT, inc);
        cudaEventRecord(evEdge[t], s1);

        cudaStreamWaitEvent(s2, evEdge[t], 0);
        emb_kernel<<<NN / 64, 256, EMB_SMEM, s2>>>(
            data_nodes + (size_t)t * NN,
            n_enc_w, n_enc_b, ee_w, ee_b,
            htOut, aggT, hn, xe);
        cudaEventRecord(evEmb[t], s2);
        node_mma6_kernel<<<dim3(NN / 64, 2), 256, NODE_SMEM, s2>>>(
            xe, w2t_n, n_b, out_w, out_b,
            hn, cn, out + (size_t)t * NN);
    }

    // ---- join back to the capture stream ----
    cudaEventRecord(evJ1, s1);
    cudaEventRecord(evJ2, s2);
    cudaStreamWaitEvent(0, evJ1, 0);
    cudaStreamWaitEvent(0, evJ2, 0);
}

// round 16
// speedup vs baseline: 1.7231x; 1.0196x over previous
#include <cuda_runtime.h>
#include <cuda_fp16.h>
#include <cstdint>

#define SSTEPS 16
#define NN 32768
#define EE 131072

// -------- persistent state (device globals; no allocation allowed) --------
__device__ __half g_hsp[(size_t)2 * EE * 64];   // ping-pong spatial h (fp16 plane)
__device__ float  g_cs[(size_t)EE * 64];
__device__ __half g_htp[(size_t)3 * NN * 64];   // triple-buffered temporal h (fp16)
__device__ float  g_ct[(size_t)NN * 64];
__device__ __half g_hnp[(size_t)2 * NN * 128];  // ping-pong node h (fp16 plane)
__device__ float  g_cn[(size_t)NN * 128];
__device__ float  g_agg2[(size_t)2 * NN * 64];  // double-buffered agg

// single-term fp16, gate-interleaved, n-major weights
__device__ __half g_w2t_s[256 * 128];
__device__ __half g_w2t_t[256 * 128];
__device__ __half g_w2t_n[512 * 256];

// node input plane: [enc(64) | emb(64)] fp16
__device__ __half g_xe[(size_t)NN * 128];

__device__ __forceinline__ float sigf(float x)   { return 1.f / (1.f + __expf(-x)); }
__device__ __forceinline__ float tanh_f(float x) { return 2.f / (1.f + __expf(-2.f * x)) - 1.f; }

__device__ __forceinline__ uint32_t smem_u32(const void* p) {
    return (uint32_t)__cvta_generic_to_shared(p);
}

#define LDSM4(r0, r1, r2, r3, addr) \
    asm volatile("ldmatrix.sync.aligned.m8n8.x4.shared.b16 {%0,%1,%2,%3},[%4];" \
                 : "=r"(r0), "=r"(r1), "=r"(r2), "=r"(r3) : "r"(addr))

#define MMA_F16(D, a0, a1, a2, a3, b0, b1) \
    asm volatile("mma.sync.aligned.m16n8k16.row.col.f32.f16.f16.f32 " \
                 "{%0,%1,%2,%3},{%4,%5,%6,%7},{%8,%9},{%0,%1,%2,%3};" \
                 : "+f"(D[0]), "+f"(D[1]), "+f"(D[2]), "+f"(D[3]) \
                 : "r"(a0), "r"(a1), "r"(a2), "r"(a3), "r"(b0), "r"(b1))

#define CP16(saddr, gptr) \
    asm volatile("cp.async.cg.shared.global [%0],[%1],16;" :: "r"(saddr), "l"(gptr))
#define CP_COMMIT() asm volatile("cp.async.commit_group;")
#define CP_WAIT0()  asm volatile("cp.async.wait_group 0;")
#define CP_WAIT1()  asm volatile("cp.async.wait_group 1;")

#define RED4(ptr, v) \
    asm volatile("red.global.add.v4.f32 [%0], {%1,%2,%3,%4};" \
                 :: "l"(ptr), "f"((v).x), "f"((v).y), "f"((v).z), "f"((v).w) : "memory")

// ============================================================================
// weight prep (single-term fp16)
// edge: rb = nh*128 + nwl*32 + g*8 + jj -> orig_n = g*64 + nh*32 + nwl*8 + jj
// ============================================================================
__global__ void prep_edge_w(const float* __restrict__ Wih, const float* __restrict__ Whh,
                            __half* __restrict__ W2t) {
    int idx = blockIdx.x * 256 + threadIdx.x;   // 256 rb * 128 k
    int rb = idx >> 7, k = idx & 127;
    int nh = rb >> 7, nwl = (rb >> 5) & 3, g = (rb >> 3) & 3, jj = rb & 7;
    int orig_n = g * 64 + nh * 32 + nwl * 8 + jj;
    float v = (k < 64) ? Wih[k * 256 + orig_n] : Whh[(k - 64) * 256 + orig_n];
    W2t[rb * 128 + k] = __float2half(v);
}

// node: rb = nh*256 + nw*64 + g*16 + jj -> orig_n = g*128 + nh*64 + nw*16 + jj
__global__ void prep_node_w(const float* __restrict__ Wih, const float* __restrict__ Whh,
                            __half* __restrict__ W2t) {
    int idx = blockIdx.x * 256 + threadIdx.x;   // 512 rb * 256 k
    int rb = idx >> 8, k = idx & 255;
    int nh = rb >> 8, nw = (rb >> 6) & 3, g = (rb >> 4) & 3, jj = rb & 15;
    int orig_n = g * 128 + nh * 64 + nw * 16 + jj;
    float v = (k < 128) ? Wih[k * 512 + orig_n] : Whh[(k - 128) * 512 + orig_n];
    W2t[rb * 256 + k] = __float2half(v);
}

// fp32 -> fp16 plane conversion (initial states); n must be multiple of 512
__global__ void cvt_f2h(const float* __restrict__ s, __half* __restrict__ d) {
    size_t i = (size_t)(blockIdx.x * 256 + threadIdx.x) * 2;
    float2 v = *(const float2*)(s + i);
    *(__half2*)(d + i) = __floats2half2_rn(v.x, v.y);
}

// ============================================================================
// Edge LSTM (hidden 64, K=128, single-term fp16), merged spatial+temporal,
// N-SPLIT grid.y=2. Block = 64 rows x 32 hidden cells (all 4 gates).
// 8 warps (2M x 4N), warp tile m32 x n32. 3 blocks/SM. (unchanged from R15)
// ============================================================================
#define E_A   0
#define E_CS  17408
#define E_INC 26624
#define E_BUF 27136
#define E_BUFSZ 10240
#define EDGE_SMEM (27136 + 3 * 10240)
#define SE_BLOCKS (EE / 64)

__global__ __launch_bounds__(256, 3) void edge_mma7_kernel(
    const float* __restrict__ x_s, const float* __restrict__ x_t,
    const float* __restrict__ encw_s, const float* __restrict__ encb_s,
    const float* __restrict__ encw_t, const float* __restrict__ encb_t,
    const __half* __restrict__ W2t_s, const __half* __restrict__ W2t_t,
    const float* __restrict__ bias_s, const float* __restrict__ bias_t,
    const __half* __restrict__ hsp_in, __half* __restrict__ hsp_out,
    float* __restrict__ c_s,
    const __half* __restrict__ htp_in, __half* __restrict__ htp_out,
    float* __restrict__ c_t,
    float* __restrict__ agg, const int* __restrict__ inc)
{
    extern __shared__ char sm[];
    const uint32_t sb = smem_u32(sm);
    const int tid = threadIdx.x;
    const int wid = tid >> 5, l = tid & 31;
    const int mw = wid & 1, nwl = wid >> 1;
    const int m0 = mw * 32;
    const int nh = blockIdx.y;

    const bool is_se = (blockIdx.x < SE_BLOCKS);
    const int row0 = (is_se ? blockIdx.x : (blockIdx.x - SE_BLOCKS)) * 64;
    const float* x    = is_se ? x_s : x_t;
    const float* encw = is_se ? encw_s : encw_t;
    const float* encb = is_se ? encb_s : encb_t;
    const __half* W2t = is_se ? W2t_s : W2t_t;
    const float* bias = is_se ? bias_s : bias_t;
    const __half* hInP = is_se ? hsp_in : htp_in;
    __half* hOutP = is_se ? hsp_out : htp_out;
    float* c = is_se ? c_s : c_t;
    float* aggp = is_se ? agg : nullptr;

    const __half* Wb = W2t + (size_t)(nh * 128) * 128;

    // ---- group 0: B chunk0 + Cs_in slice + inc + h plane (A cols 64..127) ----
    #pragma unroll
    for (int it = 0; it < 2; ++it) {
        int idx = tid + it * 256;
        int r = idx >> 2, k8 = idx & 3;
        CP16(sb + E_BUF + r * 80 + k8 * 16, Wb + (size_t)r * 128 + 0 * 32 + k8 * 8);
    }
    #pragma unroll
    for (int it = 0; it < 2; ++it) {
        int idx = tid + it * 256;
        int r = idx >> 3, seg = idx & 7;
        CP16(sb + E_CS + r * 144 + seg * 16,
             c + (size_t)(row0 + r) * 64 + nh * 32 + seg * 4);
    }
    #pragma unroll
    for (int it = 0; it < 2; ++it) {
        int idx = tid + it * 256;
        int r = idx >> 3, seg = idx & 7;
        CP16(sb + E_A + r * 272 + 128 + seg * 16,
             hInP + (size_t)(row0 + r) * 64 + seg * 8);
    }
    if (is_se && tid < 32)
        CP16(sb + E_INC + tid * 16, inc + 2 * row0 + tid * 4);
    CP_COMMIT();
    // ---- group 1: B chunk1 ----
    #pragma unroll
    for (int it = 0; it < 2; ++it) {
        int idx = tid + it * 256;
        int r = idx >> 2, k8 = idx & 3;
        CP16(sb + E_BUF + E_BUFSZ + r * 80 + k8 * 16, Wb + (size_t)r * 128 + 1 * 32 + k8 * 8);
    }
    CP_COMMIT();

    // ---- stage A enc cols 0..63 (computed, fp16) ----
    #pragma unroll
    for (int it = 0; it < 4; ++it) {
        int idx = tid + it * 256;
        int r = idx >> 4, j4 = idx & 15;
        int R = row0 + r;
        float x0 = x[R * 2 + 0], x1 = x[R * 2 + 1];
        int j = j4 * 4;
        #pragma unroll
        for (int e = 0; e < 2; ++e) {
            int cc = j + e * 2;
            float v0 = fmaxf(fmaf(x0, __ldg(&encw[cc]),     fmaf(x1, __ldg(&encw[64 + cc]),     __ldg(&encb[cc]))), 0.f);
            float v1 = fmaxf(fmaf(x0, __ldg(&encw[cc + 1]), fmaf(x1, __ldg(&encw[64 + cc + 1]), __ldg(&encb[cc + 1]))), 0.f);
            *(__half2*)(sm + E_A + r * 272 + cc * 2) = __floats2half2_rn(v0, v1);
        }
    }

    // ---- lane-constant offsets ----
    const int qi = l >> 3, ii = l & 7;
    const uint32_t b_lane = ((qi >= 2 ? 8u : 0u) + (uint32_t)ii) * 80u + (qi & 1) * 16u;
    const uint32_t a_lane = (uint32_t)(l & 15) * 272u + (uint32_t)(l >> 4) * 16u;
    const uint32_t aB = sb + E_A + m0 * 272 + a_lane;
    const uint32_t bWarp = nwl * 2560 + b_lane;

    float acc[2][4][4];
    #pragma unroll
    for (int mt = 0; mt < 2; ++mt)
        #pragma unroll
        for (int g = 0; g < 4; ++g)
            #pragma unroll
            for (int e = 0; e < 4; ++e) acc[mt][g][e] = 0.f;

    // ---- mainloop: 4 k32 chunks ----
    for (int cc = 0; cc < 4; ++cc) {
        if (cc < 3) { CP_WAIT1(); } else { CP_WAIT0(); }
        __syncthreads();

        if (cc + 2 < 4) {
            const int cn2 = cc + 2;
            const uint32_t dstb = sb + E_BUF + (cn2 % 3) * E_BUFSZ;
            #pragma unroll
            for (int it = 0; it < 2; ++it) {
                int idx = tid + it * 256;
                int r = idx >> 2, k8 = idx & 3;
                CP16(dstb + r * 80 + k8 * 16, Wb + (size_t)r * 128 + cn2 * 32 + k8 * 8);
            }
            CP_COMMIT();
        }

        const uint32_t bufB = sb + E_BUF + (cc % 3) * E_BUFSZ + bWarp;
        const uint32_t acol = (uint32_t)cc * 64;

        #pragma unroll
        for (int ks2 = 0; ks2 < 2; ++ks2) {
            uint32_t bb[4][2];
            #pragma unroll
            for (int fg = 0; fg < 2; ++fg) {
                uint32_t r0, r1, r2, r3;
                LDSM4(r0, r1, r2, r3, bufB + fg * 1280 + ks2 * 32);
                bb[fg * 2][0] = r0;     bb[fg * 2][1] = r1;
                bb[fg * 2 + 1][0] = r2; bb[fg * 2 + 1][1] = r3;
            }
            #pragma unroll
            for (int mt = 0; mt < 2; ++mt) {
                uint32_t a0, a1, a2, a3;
                LDSM4(a0, a1, a2, a3, aB + mt * 4352 + acol + ks2 * 32);
                #pragma unroll
                for (int g = 0; g < 4; ++g)
                    MMA_F16(acc[mt][g], a0, a1, a2, a3, bb[g][0], bb[g][1]);
            }
        }
    }

    // ---- epilogue: gates -> h staged in dead A region; c staged in-place ----
    __syncthreads();

    const int jl = nwl * 8 + 2 * (l & 3);
    const int j0 = nh * 32 + jl;
    const int rl_base = m0 + (l >> 2);
    #pragma unroll
    for (int mt = 0; mt < 2; ++mt) {
        #pragma unroll
        for (int rh = 0; rh < 2; ++rh) {
            int rl = rl_base + mt * 16 + rh * 8;
            float i0 = acc[mt][0][rh * 2]     + __ldg(&bias[j0]);
            float i1 = acc[mt][0][rh * 2 + 1] + __ldg(&bias[j0 + 1]);
            float f0 = acc[mt][1][rh * 2]     + __ldg(&bias[64 + j0]);
            float f1 = acc[mt][1][rh * 2 + 1] + __ldg(&bias[64 + j0 + 1]);
            float g0 = acc[mt][2][rh * 2]     + __ldg(&bias[128 + j0]);
            float g1 = acc[mt][2][rh * 2 + 1] + __ldg(&bias[128 + j0 + 1]);
            float o0 = acc[mt][3][rh * 2]     + __ldg(&bias[192 + j0]);
            float o1 = acc[mt][3][rh * 2 + 1] + __ldg(&bias[192 + j0 + 1]);
            float2 cold = *(const float2*)(sm + E_CS + rl * 144 + jl * 4);
            float c0 = sigf(f0) * cold.x + sigf(i0) * tanh_f(g0);
            float c1 = sigf(f1) * cold.y + sigf(i1) * tanh_f(g1);
            float h0 = sigf(o0) * tanh_f(c0);
            float h1 = sigf(o1) * tanh_f(c1);
            *(float2*)(sm + rl * 144 + jl * 4)         = make_float2(h0, h1);
            *(float2*)(sm + E_CS + rl * 144 + jl * 4)  = make_float2(c0, c1);
        }
    }
    __syncthreads();

    // ---- writeback: c fp32, h fp16 plane, agg vector red (32-col slice) ----
    const int* incs = (const int*)(sm + E_INC);
    #pragma unroll
    for (int p = 0; p < 2; ++p) {
        int r = p * 32 + (tid >> 3);
        int j4 = tid & 7;
        int R = row0 + r;
        float4 hv = *(const float4*)(sm + r * 144 + j4 * 16);
        float4 cv = *(const float4*)(sm + E_CS + r * 144 + j4 * 16);
        *(float4*)&c[(size_t)R * 64 + nh * 32 + j4 * 4] = cv;
        __half2 p0 = __floats2half2_rn(hv.x, hv.y);
        __half2 p1 = __floats2half2_rn(hv.z, hv.w);
        uint2 pk = make_uint2(*(uint32_t*)&p0, *(uint32_t*)&p1);
        *(uint2*)&hOutP[(size_t)R * 64 + nh * 32 + j4 * 4] = pk;
        if (aggp) {
            int n0 = incs[2 * r], n1 = incs[2 * r + 1];
            RED4(&aggp[(size_t)n0 * 64 + nh * 32 + j4 * 4], hv);
            RED4(&aggp[(size_t)n1 * 64 + nh * 32 + j4 * 4], hv);
        }
    }
}

// ============================================================================
// emb kernel: enc/emb into the fp16 plane g_xe [node][128]. No hn snapshot.
// ============================================================================
#define EMB_SMEM (64 * 132 * 4 + 128 * 64 * 4)

__global__ __launch_bounds__(256) void emb_kernel(
    const float* __restrict__ xn,
    const float* __restrict__ nencw, const float* __restrict__ nencb,
    const float* __restrict__ eew,   const float* __restrict__ eeb,
    const __half* __restrict__ htp,  const float* __restrict__ agg,
    __half* __restrict__ xe)
{
    extern __shared__ float smf[];
    float* Asf  = smf;                 // [64][132]
    float* eewS = smf + 64 * 132;      // [128][64]

    const int tid = threadIdx.x;
    const int row0 = blockIdx.x * 64;

    #pragma unroll
    for (int it = 0; it < 16; ++it) {
        int idx = tid + it * 256;
        int r = idx >> 6, j = idx & 63;
        int R = row0 + r;
        Asf[r * 132 + j]      = __half2float(htp[(size_t)R * 64 + j]);
        Asf[r * 132 + 64 + j] = agg[(size_t)R * 64 + j];
    }
    #pragma unroll
    for (int it = 0; it < 8; ++it) {
        int f4 = tid + it * 256;
        *(float4*)&eewS[f4 * 4] = *(const float4*)&eew[f4 * 4];
    }
    __syncthreads();

    const int r = tid >> 2, jq = tid & 3;
    const int R = row0 + r;

    // enc cols jq*16..+16
    {
        float xv = xn[R];
        #pragma unroll
        for (int u = 0; u < 8; ++u) {
            int cc = jq * 16 + u * 2;
            float v0 = fmaxf(fmaf(xv, __ldg(&nencw[cc]),     __ldg(&nencb[cc])), 0.f);
            float v1 = fmaxf(fmaf(xv, __ldg(&nencw[cc + 1]), __ldg(&nencb[cc + 1])), 0.f);
            *(__half2*)&xe[(size_t)R * 128 + cc] = __floats2half2_rn(v0, v1);
        }
    }

    // emb cols jq*16..+16
    {
        float accv[16];
        #pragma unroll
        for (int u = 0; u < 16; ++u) accv[u] = __ldg(&eeb[jq * 16 + u]);
        #pragma unroll 4
        for (int k = 0; k < 128; ++k) {
            float a = Asf[r * 132 + k];
            #pragma unroll
            for (int g = 0; g < 4; ++g) {
                float4 w4 = *(const float4*)&eewS[k * 64 + jq * 16 + g * 4];
                accv[g*4+0] = fmaf(a, w4.x, accv[g*4+0]);
                accv[g*4+1] = fmaf(a, w4.y, accv[g*4+1]);
                accv[g*4+2] = fmaf(a, w4.z, accv[g*4+2]);
                accv[g*4+3] = fmaf(a, w4.w, accv[g*4+3]);
            }
        }
        #pragma unroll
        for (int u = 0; u < 8; ++u) {
            float v0 = fmaxf(accv[u * 2], 0.f);
            float v1 = fmaxf(accv[u * 2 + 1], 0.f);
            int cc = 64 + jq * 16 + u * 2;
            *(__half2*)&xe[(size_t)R * 128 + cc] = __floats2half2_rn(v0, v1);
        }
    }
}

// ============================================================================
// Node LSTM GEMM (hidden 128, K=256, single-term fp16). Grid (NN/64, 2).
// A: fp16 plane [64][264]: cols 0..127 from xe, cols 128..255 from hnp_in.
// hn is a ping-pong fp16 plane (read hnp_in, write hnp_out) — no fp32 hn.
// SMEM: A 33792 | 3x Bbuf 12288.
// ============================================================================
#define N_A   0
#define N_BUF 33792
#define N_BUFSZ 12288
#define NODE_SMEM (33792 + 3 * 12288)

__global__ __launch_bounds__(256, 2) void node_mma7_kernel(
    const __half* __restrict__ xe,
    const __half* __restrict__ hnp_in, __half* __restrict__ hnp_out,
    const __half* __restrict__ W2t,
    const float* __restrict__ bias,
    const float* __restrict__ outw,  const float* __restrict__ outb,
    float* __restrict__ cn,
    float* __restrict__ out)
{
    extern __shared__ char sm[];
    const uint32_t sb = smem_u32(sm);
    const int tid = threadIdx.x;
    const int wid = tid >> 5, l = tid & 31;
    const int mw = wid & 1, nw = wid >> 1;
    const int m0 = mw * 32;
    const int row0 = blockIdx.x * 64;
    const int nh = blockIdx.y;
    const __half* Wb = W2t + (size_t)(nh * 256) * 256;

    // ---- group 0: stage A (xe cols 0..127, hnp cols 128..255) ----
    #pragma unroll
    for (int it = 0; it < 4; ++it) {
        int idx = tid + it * 256;   // 1024 = 64r x 16 k8
        int r = idx >> 4, k8 = idx & 15;
        CP16(sb + N_A + r * 528 + k8 * 16, xe + (size_t)(row0 + r) * 128 + k8 * 8);
    }
    #pragma unroll
    for (int it = 0; it < 4; ++it) {
        int idx = tid + it * 256;   // 1024 = 64r x 16 k8
        int r = idx >> 4, k8 = idx & 15;
        CP16(sb + N_A + r * 528 + 256 + k8 * 16,
             hnp_in + (size_t)(row0 + r) * 128 + k8 * 8);
    }
    CP_COMMIT();

    // ---- groups 1,2: preload B chunks 0,1 (k16 each) ----
    #pragma unroll
    for (int it = 0; it < 2; ++it) {
        int idx = tid + it * 256;
        int r = idx >> 1, k8 = idx & 1;
        CP16(sb + N_BUF + r * 48 + k8 * 16, Wb + (size_t)r * 256 + 0 * 16 + k8 * 8);
    }
    CP_COMMIT();
    #pragma unroll
    for (int it = 0; it < 2; ++it) {
        int idx = tid + it * 256;
        int r = idx >> 1, k8 = idx & 1;
        CP16(sb + N_BUF + N_BUFSZ + r * 48 + k8 * 16, Wb + (size_t)r * 256 + 1 * 16 + k8 * 8);
    }
    CP_COMMIT();

    // ---- cold (cn) register prefetch ----
    float2 cold[2][2][2];
    #pragma unroll
    for (int mt = 0; mt < 2; ++mt)
        #pragma unroll
        for (int rh = 0; rh < 2; ++rh)
            #pragma unroll
            for (int u = 0; u < 2; ++u) {
                int R = row0 + m0 + (l >> 2) + mt * 16 + rh * 8;
                int j0 = nh * 64 + nw * 16 + u * 8 + 2 * (l & 3);
                cold[mt][rh][u] = __ldg((const float2*)&cn[(size_t)R * 128 + j0]);
            }

    const int qi = l >> 3, ii = l & 7;
    const uint32_t b_lane = ((qi >= 2 ? 8u : 0u) + (uint32_t)ii) * 48u + (qi & 1) * 16u;
    const uint32_t a_lane = (uint32_t)(l & 15) * 528u + (uint32_t)(l >> 4) * 16u;
    const uint32_t aB = sb + N_A + m0 * 528 + a_lane;
    const uint32_t bWarp = nw * 3072 + b_lane;

    float acc[2][8][4];
    #pragma unroll
    for (int mt = 0; mt < 2; ++mt)
        #pragma unroll
        for (int nt = 0; nt < 8; ++nt)
            #pragma unroll
            for (int e = 0; e < 4; ++e) acc[mt][nt][e] = 0.f;

    // ---- mainloop: 16 k16 chunks ----
    for (int cc = 0; cc < 16; ++cc) {
        if (cc < 15) { CP_WAIT1(); } else { CP_WAIT0(); }
        __syncthreads();

        if (cc + 2 < 16) {
            const int cn2 = cc + 2;
            const uint32_t dstb = sb + N_BUF + (cn2 % 3) * N_BUFSZ;
            #pragma unroll
            for (int it = 0; it < 2; ++it) {
                int idx = tid + it * 256;
                int r = idx >> 1, k8 = idx & 1;
                CP16(dstb + r * 48 + k8 * 16, Wb + (size_t)r * 256 + cn2 * 16 + k8 * 8);
            }
            CP_COMMIT();
        }

        const uint32_t bufB = sb + N_BUF + (cc % 3) * N_BUFSZ + bWarp;
        const uint32_t acol = (uint32_t)cc * 32;

        uint32_t bb[8][2];
        #pragma unroll
        for (int fg = 0; fg < 4; ++fg) {
            uint32_t r0, r1, r2, r3;
            LDSM4(r0, r1, r2, r3, bufB + fg * 768);
            bb[fg * 2][0] = r0;     bb[fg * 2][1] = r1;
            bb[fg * 2 + 1][0] = r2; bb[fg * 2 + 1][1] = r3;
        }
        #pragma unroll
        for (int mt = 0; mt < 2; ++mt) {
            uint32_t a0, a1, a2, a3;
            LDSM4(a0, a1, a2, a3, aB + mt * 8448 + acol);
            #pragma unroll
            for (int nt = 0; nt < 8; ++nt)
                MMA_F16(acc[mt][nt], a0, a1, a2, a3, bb[nt][0], bb[nt][1]);
        }
    }

    // ---- epilogue: gates -> staged h/c (272B stride; A + dead ring) ----
    __syncthreads();

    const float ob = (nh == 0 && nw == 0) ? __ldg(outb) : 0.f;
    const int rl_base = m0 + (l >> 2);
    #pragma unroll
    for (int mt = 0; mt < 2; ++mt) {
        #pragma unroll
        for (int rh = 0; rh < 2; ++rh) {
            int rl = rl_base + mt * 16 + rh * 8;
            int R = row0 + rl;
            float po = 0.f;
            #pragma unroll
            for (int u = 0; u < 2; ++u) {
                int j0 = nh * 64 + nw * 16 + u * 8 + 2 * (l & 3);
                int jl = j0 - nh * 64;
                float i0 = acc[mt][u][rh * 2]          + __ldg(&bias[j0]);
                float i1 = acc[mt][u][rh * 2 + 1]      + __ldg(&bias[j0 + 1]);
                float f0 = acc[mt][2 + u][rh * 2]      + __ldg(&bias[128 + j0]);
                float f1 = acc[mt][2 + u][rh * 2 + 1]  + __ldg(&bias[128 + j0 + 1]);
                float g0 = acc[mt][4 + u][rh * 2]      + __ldg(&bias[256 + j0]);
                float g1 = acc[mt][4 + u][rh * 2 + 1]  + __ldg(&bias[256 + j0 + 1]);
                float o0 = acc[mt][6 + u][rh * 2]      + __ldg(&bias[384 + j0]);
                float o1 = acc[mt][6 + u][rh * 2 + 1]  + __ldg(&bias[384 + j0 + 1]);
                float2 cv = cold[mt][rh][u];
                float c0 = sigf(f0) * cv.x + sigf(i0) * tanh_f(g0);
                float c1 = sigf(f1) * cv.y + sigf(i1) * tanh_f(g1);
                float h0 = sigf(o0) * tanh_f(c0);
                float h1 = sigf(o1) * tanh_f(c1);
                *(float2*)(sm + rl * 272 + jl * 4)         = make_float2(h0, h1);
                *(float2*)(sm + 17408 + rl * 272 + jl * 4) = make_float2(c0, c1);
                po = fmaf(h0, __ldg(&outw[j0]), po);
                po = fmaf(h1, __ldg(&outw[j0 + 1]), po);
            }
            po += __shfl_xor_sync(0xffffffffu, po, 1);
            po += __shfl_xor_sync(0xffffffffu, po, 2);
            if ((l & 3) == 0) atomicAdd(&out[R], po + ob);
        }
    }
    __syncthreads();

    // ---- writeback: cn fp32, hn fp16 plane ----
    #pragma unroll
    for (int p = 0; p < 4; ++p) {
        int r = p * 16 + (tid >> 4);
        int j4 = tid & 15;
        int R = row0 + r;
        float4 hv = *(const float4*)(sm + r * 272 + j4 * 16);
        float4 cv = *(const float4*)(sm + 17408 + r * 272 + j4 * 16);
        *(float4*)&cn[(size_t)R * 128 + nh * 64 + j4 * 4] = cv;
        __half2 q0 = __floats2half2_rn(hv.x, hv.y);
        __half2 q1 = __floats2half2_rn(hv.z, hv.w);
        uint2 pk = make_uint2(*(uint32_t*)&q0, *(uint32_t*)&q1);
        *(uint2*)&hnp_out[(size_t)R * 128 + nh * 64 + j4 * 4] = pk;
    }
}

// ============================================================================
extern "C" void kernel_launch(void* const* d_in, const int* in_sizes, int n_in,
                              void* d_out, int out_size) {
    const float* data_nodes = (const float*)d_in[0];
    const float* data_te    = (const float*)d_in[1];
    const float* data_se    = (const float*)d_in[2];
    const float* h_n0 = (const float*)d_in[3];
    const float* c_n0 = (const float*)d_in[4];
    const float* h_t0 = (const float*)d_in[5];
    const float* c_t0 = (const float*)d_in[6];
    const float* h_s0 = (const float*)d_in[7];
    const float* c_s0 = (const float*)d_in[8];
    const int*   inc  = (const int*)d_in[9];
    const float* t_enc_w = (const float*)d_in[10];
    const float* t_enc_b = (const float*)d_in[11];
    const float* t_Wih   = (const float*)d_in[12];
    const float* t_Whh   = (const float*)d_in[13];
    const float* t_b     = (const float*)d_in[14];
    const float* s_enc_w = (const float*)d_in[15];
    const float* s_enc_b = (const float*)d_in[16];
    const float* s_Wih   = (const float*)d_in[17];
    const float* s_Whh   = (const float*)d_in[18];
    const float* s_b     = (const float*)d_in[19];
    const float* n_enc_w = (const float*)d_in[20];
    const float* n_enc_b = (const float*)d_in[21];
    const float* ee_w    = (const float*)d_in[22];
    const float* ee_b    = (const float*)d_in[23];
    const float* n_Wih   = (const float*)d_in[24];
    const float* n_Whh   = (const float*)d_in[25];
    const float* n_b     = (const float*)d_in[26];
    const float* out_w   = (const float*)d_in[27];
    const float* out_b   = (const float*)d_in[28];
    float* out = (float*)d_out;

    float *cs, *ct, *cn, *agg2;
    __half *hsp, *htp, *hnp, *w2t_s, *w2t_t, *w2t_n, *xe;
    cudaGetSymbolAddress((void**)&hsp, g_hsp);
    cudaGetSymbolAddress((void**)&cs,  g_cs);
    cudaGetSymbolAddress((void**)&htp, g_htp);
    cudaGetSymbolAddress((void**)&ct,  g_ct);
    cudaGetSymbolAddress((void**)&hnp, g_hnp);
    cudaGetSymbolAddress((void**)&cn,  g_cn);
    cudaGetSymbolAddress((void**)&agg2, g_agg2);
    cudaGetSymbolAddress((void**)&w2t_s, g_w2t_s);
    cudaGetSymbolAddress((void**)&w2t_t, g_w2t_t);
    cudaGetSymbolAddress((void**)&w2t_n, g_w2t_n);
    cudaGetSymbolAddress((void**)&xe, g_xe);

    static bool s_init = false;
    static cudaStream_t s1, s2;
    static cudaEvent_t evRoot, evJ1, evJ2;
    static cudaEvent_t evEdge[SSTEPS], evEmb[SSTEPS];
    if (!s_init) {
        s_init = true;
        cudaStreamCreateWithFlags(&s1, cudaStreamNonBlocking);
        cudaStreamCreateWithFlags(&s2, cudaStreamNonBlocking);
        cudaEventCreateWithFlags(&evRoot, cudaEventDisableTiming);
        cudaEventCreateWithFlags(&evJ1, cudaEventDisableTiming);
        cudaEventCreateWithFlags(&evJ2, cudaEventDisableTiming);
        for (int t = 0; t < SSTEPS; ++t) {
            cudaEventCreateWithFlags(&evEdge[t], cudaEventDisableTiming);
            cudaEventCreateWithFlags(&evEmb[t], cudaEventDisableTiming);
        }
        cudaFuncSetAttribute(edge_mma7_kernel, cudaFuncAttributeMaxDynamicSharedMemorySize, EDGE_SMEM);
        cudaFuncSetAttribute(node_mma7_kernel, cudaFuncAttributeMaxDynamicSharedMemorySize, NODE_SMEM);
        cudaFuncSetAttribute(emb_kernel,       cudaFuncAttributeMaxDynamicSharedMemorySize, EMB_SMEM);
    }

    // ---- prologue on the capture (default) stream ----
    cudaMemcpyAsync(cs, c_s0, (size_t)EE * 64  * 4, cudaMemcpyDeviceToDevice);
    cudaMemcpyAsync(ct, c_t0, (size_t)NN * 64  * 4, cudaMemcpyDeviceToDevice);
    cudaMemcpyAsync(cn, c_n0, (size_t)NN * 128 * 4, cudaMemcpyDeviceToDevice);
    cudaMemsetAsync(out, 0, (size_t)SSTEPS * NN * 4);
    cudaMemsetAsync(agg2, 0, (size_t)2 * NN * 64 * 4);   // both agg buffers

    cvt_f2h<<<EE * 64 / 512, 256>>>(h_s0, hsp);          // spatial h plane, buf 0
    cvt_f2h<<<NN * 64 / 512, 256>>>(h_t0, htp);          // temporal h plane, buf 0
    cvt_f2h<<<NN * 128 / 512, 256>>>(h_n0, hnp);         // node h plane, buf 0
    prep_edge_w<<<128, 256>>>(s_Wih, s_Whh, w2t_s);
    prep_edge_w<<<128, 256>>>(t_Wih, t_Whh, w2t_t);
    prep_node_w<<<512, 256>>>(n_Wih, n_Whh, w2t_n);

    // ---- fork ----
    cudaEventRecord(evRoot, 0);
    cudaStreamWaitEvent(s1, evRoot, 0);
    cudaStreamWaitEvent(s2, evRoot, 0);

    const int edge_grid_x = SE_BLOCKS + NN / 64;   // 2048 + 512
    const size_t HTB = (size_t)NN * 64;
    const size_t HSB = (size_t)EE * 64;
    const size_t HNB = (size_t)NN * 128;

    for (int t = 0; t < SSTEPS; ++t) {
        float* aggT  = agg2 + (size_t)(t & 1) * HTB;
        __half* htIn  = htp + (size_t)(t % 3) * HTB;
        __half* htOut = htp + (size_t)((t + 1) % 3) * HTB;
        __half* hsIn  = hsp + (size_t)(t & 1) * HSB;
        __half* hsOut = hsp + (size_t)((t + 1) & 1) * HSB;
        __half* hnIn  = hnp + (size_t)(t & 1) * HNB;
        __half* hnOut = hnp + (size_t)((t + 1) & 1) * HNB;

        // stream 1: edge only (agg buffer was zeroed on s2 two steps ago)
        if (t >= 2) cudaStreamWaitEvent(s1, evEmb[t - 2], 0);
        edge_mma7_kernel<<<dim3(edge_grid_x, 2), 256, EDGE_SMEM, s1>>>(
            data_se + (size_t)t * EE * 2, data_te + (size_t)t * NN * 2,
            s_enc_w, s_enc_b, t_enc_w, t_enc_b,
            w2t_s, w2t_t, s_b, t_b,
            hsIn, hsOut, cs, htIn, htOut, ct, aggT, inc);
        cudaEventRecord(evEdge[t], s1);

        // stream 2: emb (consumes agg) -> zero agg for reuse -> node
        cudaStreamWaitEvent(s2, evEdge[t], 0);
        emb_kernel<<<NN / 64, 256, EMB_SMEM, s2>>>(
            data_nodes + (size_t)t * NN,
            n_enc_w, n_enc_b, ee_w, ee_b,
            htOut, aggT, xe);
        cudaMemsetAsync(aggT, 0, HTB * 4, s2);
        cudaEventRecord(evEmb[t], s2);
        node_mma7_kernel<<<dim3(NN / 64, 2), 256, NODE_SMEM, s2>>>(
            xe, hnIn, hnOut, w2t_n, n_b, out_w, out_b,
            cn, out + (size_t)t * NN);
    }

    // ---- join back to the capture stream ----
    cudaEventRecord(evJ1, s1);
    cudaEventRecord(evJ2, s2);
    cudaStreamWaitEvent(0, evJ1, 0);
    cudaStreamWaitEvent(0, evJ2, 0);
}